// round 12
// baseline (speedup 1.0000x reference)
#include <cuda_runtime.h>
#include <cstdint>

#define SROW 36
#define MAXN 50048
#define MAXE 800032
typedef unsigned long long ull;

__device__ float g_node[(size_t)MAXN * 128];
__device__ float g_edge_tail[(size_t)MAXE * 64];
__device__ float g_agg[(size_t)MAXN * 64];
__device__ float g_counts[MAXN];
__device__ float g_W0T[128 * 192];   // core_e_W0^T [n=128][k=192], tf32-rounded
__device__ float g_W1T[64 * 128];    // core_e_W1^T [n=64][k=128]
__device__ float g_eW0T[128 * 8];    // enc_e_W0^T  [n=128][k=8 pad]
__device__ float g_eW1T[64 * 128];   // enc_e_W1[:,64:]^T

// ---------------- tf32 mma.sync helpers ----------------
__device__ __forceinline__ uint32_t f2tf(float x) {
    uint32_t u; asm("cvt.rna.tf32.f32 %0, %1;" : "=r"(u) : "f"(x));
    return u;
}
#define MMA8(d, a0, a1, a2, a3, b0, b1)                                        \
    asm volatile(                                                              \
        "mma.sync.aligned.m16n8k8.row.col.f32.tf32.tf32.f32 "                  \
        "{%0,%1,%2,%3}, {%4,%5,%6,%7}, {%8,%9}, {%0,%1,%2,%3};"                \
        : "+f"((d)[0]), "+f"((d)[1]), "+f"((d)[2]), "+f"((d)[3])               \
        : "r"(a0), "r"(a1), "r"(a2), "r"(a3), "r"(b0), "r"(b1))
#define REDV4(p, x0, x1, x2, x3)                                               \
    asm volatile("red.global.add.v4.f32 [%0], {%1,%2,%3,%4};"                  \
        :: "l"(p), "f"(x0), "f"(x1), "f"(x2), "f"(x3) : "memory")

// ---------------- small kernels ----------------
__global__ void k_prep(const float* __restrict__ ceW0, const float* __restrict__ ceW1,
                       const float* __restrict__ eeW0, const float* __restrict__ eeW1) {
    int i = blockIdx.x * 256 + threadIdx.x;
    if (i < 128 * 192) { int n = i / 192, k = i % 192; g_W0T[i] = __uint_as_float(f2tf(ceW0[k * 128 + n])); }
    int j = i - 128 * 192;
    if (j >= 0 && j < 64 * 128) { int n = j / 128, k = j % 128; g_W1T[j] = __uint_as_float(f2tf(ceW1[k * 64 + n])); }
    int m = j - 64 * 128;
    if (m >= 0 && m < 128 * 8) { int n = m / 8, k = m % 8; g_eW0T[m] = (k < 3) ? __uint_as_float(f2tf(eeW0[k * 128 + n])) : 0.f; }
    int q = m - 128 * 8;
    if (q >= 0 && q < 64 * 128) { int n = q / 128, k = q % 128; g_eW1T[q] = __uint_as_float(f2tf(eeW1[k * 128 + 64 + n])); }
}
__global__ void k_zero_counts(int n) { int i = blockIdx.x*256+threadIdx.x; if (i < n) g_counts[i] = 0.f; }
__global__ void k_zero_agg(int n)    { int i = blockIdx.x*256+threadIdx.x; if (i < n) g_agg[i] = 0.f; }
__global__ void k_counts(const int* __restrict__ ei, int E) {
    int e = blockIdx.x*256+threadIdx.x;
    if (e < E) atomicAdd(&g_counts[ei[E + e]], 1.0f);
}

// ---------------------------------------------------------------------------
// core edge step, tensor (tf32 mma.sync), vectorized-red epilogue
// smem: sW0[128][196] | sW1[64][132] | sA[128][68] | idx[256] | b0[128] | b1[64]
// ---------------------------------------------------------------------------
#define T_CORE 8
#define W1_OFF 25088
#define A_OFF  33536
#define IDX_OFF 42240
#define B0_OFF 42496
#define B1_OFF 42624
__global__ void __launch_bounds__(256, 1)
k_edge_core_mma(const int* __restrict__ ei, const float* __restrict__ b0g,
                const float* __restrict__ b1g, int E) {
    extern __shared__ float sm[];
    float* sW0 = sm;
    float* sW1 = sm + W1_OFF;
    float* sA  = sm + A_OFF;
    int*   sIdx = (int*)(sm + IDX_OFF);
    float* sB0 = sm + B0_OFF;
    float* sB1 = sm + B1_OFF;
    int t = threadIdx.x, w = t >> 5, lane = t & 31;
    int tg = lane & 3, lg = lane >> 2, rb = 16 * w;

    for (int i = t; i < 128 * 48; i += 256) {
        int n = i / 48, j = i % 48;
        *(float4*)(sW0 + n * 196 + j * 4) = *(const float4*)(g_W0T + n * 192 + j * 4);
    }
    for (int i = t; i < 64 * 32; i += 256) {
        int n = i / 32, j = i % 32;
        *(float4*)(sW1 + n * 132 + j * 4) = *(const float4*)(g_W1T + n * 128 + j * 4);
    }
    if (t < 128) sB0[t] = b0g[t];
    if (t < 64)  sB1[t] = b1g[t];
    __syncthreads();

    for (int tt = 0; tt < T_CORE; tt++) {
        int base = (blockIdx.x * T_CORE + tt) * 128;
        if (base >= E) break;
        __syncthreads();
        if (t < 128) {
            int e = min(base + t, E - 1);
            sIdx[t] = ei[E + e];
            sIdx[128 + t] = ei[e];
        }
        __syncthreads();

        float d1[16][4];
#pragma unroll
        for (int n0 = 0; n0 < 16; n0++)
#pragma unroll
            for (int c = 0; c < 4; c++) d1[n0][c] = 0.f;

        int row = t >> 1, half = t & 1;
        int er = min(base + row, E - 1);

        for (int ch = 0; ch < 3; ch++) {
            const float* p;
            if (ch == 0)      p = g_edge_tail + (size_t)er * 64;
            else if (ch == 1) p = g_node + (size_t)sIdx[row] * 128 + 64;
            else              p = g_node + (size_t)sIdx[128 + row] * 128 + 64;
            p += half * 32;
            float* dst = sA + row * 68 + half * 32;
#pragma unroll
            for (int j = 0; j < 8; j++) {
                float4 v = *(const float4*)(p + j * 4);
                *(float4*)(dst + j * 4) = make_float4(
                    __uint_as_float(f2tf(v.x)), __uint_as_float(f2tf(v.y)),
                    __uint_as_float(f2tf(v.z)), __uint_as_float(f2tf(v.w)));
            }
            __syncwarp();
            for (int k0 = 0; k0 < 8; k0++) {
                int kb = k0 * 8 + tg;
                uint32_t a0 = __float_as_uint(sA[(rb + lg) * 68 + kb]);
                uint32_t a1 = __float_as_uint(sA[(rb + lg + 8) * 68 + kb]);
                uint32_t a2 = __float_as_uint(sA[(rb + lg) * 68 + kb + 4]);
                uint32_t a3 = __float_as_uint(sA[(rb + lg + 8) * 68 + kb + 4]);
                int kg = ch * 64 + k0 * 8 + tg;
#pragma unroll
                for (int n0 = 0; n0 < 16; n0++) {
                    uint32_t b0 = __float_as_uint(sW0[(n0 * 8 + lg) * 196 + kg]);
                    uint32_t b1 = __float_as_uint(sW0[(n0 * 8 + lg) * 196 + kg + 4]);
                    MMA8(d1[n0], a0, a1, a2, a3, b0, b1);
                }
            }
            __syncwarp();
        }

        float d2[8][4];
#pragma unroll
        for (int n0 = 0; n0 < 8; n0++)
#pragma unroll
            for (int c = 0; c < 4; c++) d2[n0][c] = 0.f;

        for (int nh = 0; nh < 2; nh++) {
#pragma unroll
            for (int q = 0; q < 8; q++) {
                int n0 = nh * 8 + q;
                int c0 = n0 * 8 + 2 * tg, cl = c0 - nh * 64;
                float ba = sB0[c0], bb = sB0[c0 + 1];
                float h0 = fmaxf(d1[n0][0] + ba, 0.f), h1 = fmaxf(d1[n0][1] + bb, 0.f);
                float h2 = fmaxf(d1[n0][2] + ba, 0.f), h3 = fmaxf(d1[n0][3] + bb, 0.f);
                *(float2*)(sA + (rb + lg) * 68 + cl) =
                    make_float2(__uint_as_float(f2tf(h0)), __uint_as_float(f2tf(h1)));
                *(float2*)(sA + (rb + lg + 8) * 68 + cl) =
                    make_float2(__uint_as_float(f2tf(h2)), __uint_as_float(f2tf(h3)));
            }
            __syncwarp();
            for (int k0 = 0; k0 < 8; k0++) {
                int kb = k0 * 8 + tg;
                uint32_t a0 = __float_as_uint(sA[(rb + lg) * 68 + kb]);
                uint32_t a1 = __float_as_uint(sA[(rb + lg + 8) * 68 + kb]);
                uint32_t a2 = __float_as_uint(sA[(rb + lg) * 68 + kb + 4]);
                uint32_t a3 = __float_as_uint(sA[(rb + lg + 8) * 68 + kb + 4]);
                int kg = nh * 64 + k0 * 8 + tg;
#pragma unroll
                for (int n0 = 0; n0 < 8; n0++) {
                    uint32_t b0 = __float_as_uint(sW1[(n0 * 8 + lg) * 132 + kg]);
                    uint32_t b1 = __float_as_uint(sW1[(n0 * 8 + lg) * 132 + kg + 4]);
                    MMA8(d2[n0], a0, a1, a2, a3, b0, b1);
                }
            }
            __syncwarp();
        }

        // stage D2 into warp band of sA (h no longer needed)
#pragma unroll
        for (int n0 = 0; n0 < 8; n0++) {
            int c = n0 * 8 + 2 * tg;
            *(float2*)(sA + (rb + lg) * 68 + c)     = make_float2(d2[n0][0], d2[n0][1]);
            *(float2*)(sA + (rb + lg + 8) * 68 + c) = make_float2(d2[n0][2], d2[n0][3]);
        }
        __syncwarp();

        // vectorized epilogue: lane owns row rb+(lane>>1), col half (lane&1)*32
        {
            int rloc = rb + (lane >> 1);
            int e = base + rloc;
            if (e < E) {
                int cb = (lane & 1) * 32;
                int dn = sIdx[rloc];
                float* pt = g_edge_tail + (size_t)e * 64 + cb;
                float* pa = g_agg + (size_t)dn * 64 + cb;
#pragma unroll
                for (int q = 0; q < 8; q++) {
                    float4 d = *(const float4*)(sA + rloc * 68 + cb + q * 4);
                    float4 bi = *(const float4*)(sB1 + cb + q * 4);
                    float4 rv = *(const float4*)(pt + q * 4);
                    float x0 = d.x + bi.x + rv.x, x1 = d.y + bi.y + rv.y;
                    float x2 = d.z + bi.z + rv.z, x3 = d.w + bi.w + rv.w;
                    *(float4*)(pt + q * 4) = make_float4(x0, x1, x2, x3);
                    REDV4(pa + q * 4, x0, x1, x2, x3);
                }
            }
        }
        __syncwarp();
    }
}

// ---------------------------------------------------------------------------
// encode edge, tensor: ef (K=3 pad 8) -> 128 relu -> cols 64..127
// ---------------------------------------------------------------------------
#define T_ENC 8
#define EW1_OFF 1536
#define EA_OFF  9984
__global__ void __launch_bounds__(256, 1)
k_encode_edge_mma(const float* __restrict__ ef, const float* __restrict__ b0g,
                  const float* __restrict__ b1g, int E) {
    extern __shared__ float sm[];
    float* sW0 = sm;
    float* sW1 = sm + EW1_OFF;
    float* sA  = sm + EA_OFF;
    int t = threadIdx.x, w = t >> 5, lane = t & 31;
    int tg = lane & 3, lg = lane >> 2, rb = 16 * w;

    for (int i = t; i < 128 * 2; i += 256) {
        int n = i / 2, j = i % 2;
        *(float4*)(sW0 + n * 12 + j * 4) = *(const float4*)(g_eW0T + n * 8 + j * 4);
    }
    for (int i = t; i < 64 * 32; i += 256) {
        int n = i / 32, j = i % 32;
        *(float4*)(sW1 + n * 132 + j * 4) = *(const float4*)(g_eW1T + n * 128 + j * 4);
    }
    __syncthreads();

    for (int tt = 0; tt < T_ENC; tt++) {
        int base = (blockIdx.x * T_ENC + tt) * 128;
        if (base >= E) break;
        int row = t >> 1, half = t & 1;
        int er = min(base + row, E - 1);
        {
            float* dst = sA + row * 68 + half * 4;
            if (half == 0) {
                *(float4*)dst = make_float4(
                    __uint_as_float(f2tf(ef[er * 3 + 0])),
                    __uint_as_float(f2tf(ef[er * 3 + 1])),
                    __uint_as_float(f2tf(ef[er * 3 + 2])), 0.f);
            } else {
                *(float4*)dst = make_float4(0.f, 0.f, 0.f, 0.f);
            }
        }
        __syncwarp();

        float d1[16][4];
#pragma unroll
        for (int n0 = 0; n0 < 16; n0++)
#pragma unroll
            for (int c = 0; c < 4; c++) d1[n0][c] = 0.f;
        {
            uint32_t a0 = __float_as_uint(sA[(rb + lg) * 68 + tg]);
            uint32_t a1 = __float_as_uint(sA[(rb + lg + 8) * 68 + tg]);
            uint32_t a2 = __float_as_uint(sA[(rb + lg) * 68 + tg + 4]);
            uint32_t a3 = __float_as_uint(sA[(rb + lg + 8) * 68 + tg + 4]);
#pragma unroll
            for (int n0 = 0; n0 < 16; n0++) {
                uint32_t b0 = __float_as_uint(sW0[(n0 * 8 + lg) * 12 + tg]);
                uint32_t b1 = __float_as_uint(sW0[(n0 * 8 + lg) * 12 + tg + 4]);
                MMA8(d1[n0], a0, a1, a2, a3, b0, b1);
            }
        }
        __syncwarp();

        float d2[8][4];
#pragma unroll
        for (int n0 = 0; n0 < 8; n0++)
#pragma unroll
            for (int c = 0; c < 4; c++) d2[n0][c] = 0.f;

        for (int nh = 0; nh < 2; nh++) {
#pragma unroll
            for (int q = 0; q < 8; q++) {
                int n0 = nh * 8 + q;
                int c0 = n0 * 8 + 2 * tg, cl = c0 - nh * 64;
                float ba = __ldg(b0g + c0), bb = __ldg(b0g + c0 + 1);
                float h0 = fmaxf(d1[n0][0] + ba, 0.f), h1 = fmaxf(d1[n0][1] + bb, 0.f);
                float h2 = fmaxf(d1[n0][2] + ba, 0.f), h3 = fmaxf(d1[n0][3] + bb, 0.f);
                *(float2*)(sA + (rb + lg) * 68 + cl) =
                    make_float2(__uint_as_float(f2tf(h0)), __uint_as_float(f2tf(h1)));
                *(float2*)(sA + (rb + lg + 8) * 68 + cl) =
                    make_float2(__uint_as_float(f2tf(h2)), __uint_as_float(f2tf(h3)));
            }
            __syncwarp();
            for (int k0 = 0; k0 < 8; k0++) {
                int kb = k0 * 8 + tg;
                uint32_t a0 = __float_as_uint(sA[(rb + lg) * 68 + kb]);
                uint32_t a1 = __float_as_uint(sA[(rb + lg + 8) * 68 + kb]);
                uint32_t a2 = __float_as_uint(sA[(rb + lg) * 68 + kb + 4]);
                uint32_t a3 = __float_as_uint(sA[(rb + lg + 8) * 68 + kb + 4]);
                int kg = nh * 64 + k0 * 8 + tg;
#pragma unroll
                for (int n0 = 0; n0 < 8; n0++) {
                    uint32_t b0 = __float_as_uint(sW1[(n0 * 8 + lg) * 132 + kg]);
                    uint32_t b1 = __float_as_uint(sW1[(n0 * 8 + lg) * 132 + kg + 4]);
                    MMA8(d2[n0], a0, a1, a2, a3, b0, b1);
                }
            }
            __syncwarp();
        }

        int r0 = rb + lg, r1 = r0 + 8;
#pragma unroll
        for (int n0 = 0; n0 < 8; n0++) {
            int c = n0 * 8 + 2 * tg;
            float ba = __ldg(b1g + c), bb = __ldg(b1g + c + 1);
            int e0 = base + r0;
            if (e0 < E)
                *(float2*)(g_edge_tail + (size_t)e0 * 64 + c) =
                    make_float2(d2[n0][0] + ba, d2[n0][1] + bb);
            int e1 = base + r1;
            if (e1 < E)
                *(float2*)(g_edge_tail + (size_t)e1 * 64 + c) =
                    make_float2(d2[n0][2] + ba, d2[n0][3] + bb);
        }
        __syncwarp();
    }
}

// ---------------- scalar fp32 node-side ----------------
__device__ __forceinline__ ull pk2(float a, float b) { ull r; asm("mov.b64 %0, {%1, %2};" : "=l"(r) : "f"(a), "f"(b)); return r; }
__device__ __forceinline__ void upk2(ull v, float &a, float &b) { asm("mov.b64 {%0, %1}, %2;" : "=f"(a), "=f"(b) : "l"(v)); }
__device__ __forceinline__ void fma2(ull &d, ull a, ull b) { asm("fma.rn.f32x2 %0, %1, %2, %3;" : "=l"(d) : "l"(a), "l"(b), "l"(d)); }
__device__ __forceinline__ ull add2(ull a, ull b) { ull r; asm("add.rn.f32x2 %0, %1, %2;" : "=l"(r) : "l"(a), "l"(b)); return r; }
__device__ __forceinline__ void gemmA(ull (&acc)[4][4], const float* __restrict__ W, int ld, int K,
                                      const float* sInT, int c0, int r0) {
#pragma unroll 4
    for (int k = 0; k < K; k++) {
        float4 w = __ldg(reinterpret_cast<const float4*>(W + (size_t)k * ld + c0));
        ull w0 = pk2(w.x, w.x), w1 = pk2(w.y, w.y), w2 = pk2(w.z, w.z), w3 = pk2(w.w, w.w);
        const float* row = sInT + k * SROW + r0;
        ulonglong2 xa = *reinterpret_cast<const ulonglong2*>(row);
        ulonglong2 xb = *reinterpret_cast<const ulonglong2*>(row + 4);
        fma2(acc[0][0], xa.x, w0); fma2(acc[0][1], xa.x, w1); fma2(acc[0][2], xa.x, w2); fma2(acc[0][3], xa.x, w3);
        fma2(acc[1][0], xa.y, w0); fma2(acc[1][1], xa.y, w1); fma2(acc[1][2], xa.y, w2); fma2(acc[1][3], xa.y, w3);
        fma2(acc[2][0], xb.x, w0); fma2(acc[2][1], xb.x, w1); fma2(acc[2][2], xb.x, w2); fma2(acc[2][3], xb.x, w3);
        fma2(acc[3][0], xb.y, w0); fma2(acc[3][1], xb.y, w1); fma2(acc[3][2], xb.y, w2); fma2(acc[3][3], xb.y, w3);
    }
}
__device__ __forceinline__ void gemmB(ull (&acc)[2][4], const float* __restrict__ W, int ld, int K,
                                      const float* sInT, int c0, int r0) {
#pragma unroll 4
    for (int k = 0; k < K; k++) {
        float4 w = __ldg(reinterpret_cast<const float4*>(W + (size_t)k * ld + c0));
        ull w0 = pk2(w.x, w.x), w1 = pk2(w.y, w.y), w2 = pk2(w.z, w.z), w3 = pk2(w.w, w.w);
        ulonglong2 xa = *reinterpret_cast<const ulonglong2*>(sInT + k * SROW + r0);
        fma2(acc[0][0], xa.x, w0); fma2(acc[0][1], xa.x, w1); fma2(acc[0][2], xa.x, w2); fma2(acc[0][3], xa.x, w3);
        fma2(acc[1][0], xa.y, w0); fma2(acc[1][1], xa.y, w1); fma2(acc[1][2], xa.y, w2); fma2(acc[1][3], xa.y, w3);
    }
}
template <int NP>
__device__ __forceinline__ void init_bias(ull (&acc)[NP][4], const float* __restrict__ b, int c0) {
#pragma unroll
    for (int c = 0; c < 4; c++) {
        float bv = b[c0 + c]; ull bb = pk2(bv, bv);
#pragma unroll
        for (int p = 0; p < NP; p++) acc[p][c] = bb;
    }
}
__device__ __forceinline__ void relu_store_hT(ull (&acc)[4][4], float* sHT, int c0, int r0) {
#pragma unroll
    for (int p = 0; p < 4; p++)
#pragma unroll
        for (int c = 0; c < 4; c++) {
            float a, b; upk2(acc[p][c], a, b);
            *reinterpret_cast<float2*>(&sHT[(c0 + c) * SROW + r0 + 2 * p]) =
                make_float2(fmaxf(a, 0.f), fmaxf(b, 0.f));
        }
}

__global__ void __launch_bounds__(128)
k_encode_node(const float* __restrict__ nf, const float* __restrict__ emb,
              const float* __restrict__ W0, const float* __restrict__ b0,
              const float* __restrict__ W1, const float* __restrict__ b1, int N) {
    __shared__ float sInT[47 * SROW];
    __shared__ float sHT[128 * SROW];
    __shared__ int sPT[32];
    int t = threadIdx.x, base = blockIdx.x * 32;
    if (t < 32) { int n = min(base + t, N - 1); sPT[t] = (int)(nf[n * 32 + 31] + 0.5f); }
    __syncthreads();
    for (int i = t; i < 32 * 47; i += 128) {
        int r = i / 47, k = i - r * 47;
        int n = min(base + r, N - 1);
        sInT[k * SROW + r] = (k < 31) ? nf[n * 32 + k] : emb[sPT[r] * 16 + (k - 31)];
    }
    __syncthreads();
    int w = t >> 5, l = t & 31;
    int c0 = 32 * w + (l & 7) * 4, r0 = (l >> 3) * 8;
    ull acc[4][4];
    init_bias<4>(acc, b0, c0);
    gemmA(acc, W0, 128, 47, sInT, c0, r0);
    relu_store_hT(acc, sHT, c0, r0);
    __syncthreads();
    ull acc2[4][4];
    init_bias<4>(acc2, b1, c0);
    gemmA(acc2, W1, 128, 128, sHT, c0, r0);
#pragma unroll
    for (int p = 0; p < 4; p++)
#pragma unroll
        for (int c = 0; c < 4; c++) {
            float a, b; upk2(acc2[p][c], a, b);
            int rA = base + r0 + 2 * p;
            if (rA < N)     g_node[(size_t)rA * 128 + c0 + c] = a;
            if (rA + 1 < N) g_node[(size_t)(rA + 1) * 128 + c0 + c] = b;
        }
}

__global__ void __launch_bounds__(128)
k_node_core(const float* __restrict__ W0, const float* __restrict__ b0,
            const float* __restrict__ W1, const float* __restrict__ b1, int N) {
    __shared__ float sInT[128 * SROW];
    __shared__ float sHT[128 * SROW];
    __shared__ float sInv[32];
    int t = threadIdx.x, base = blockIdx.x * 32;
    if (t < 32) { int n = min(base + t, N - 1); sInv[t] = 1.0f / fmaxf(g_counts[n], 1.0f); }
    __syncthreads();
    for (int i = t; i < 32 * 128; i += 128) {
        int r = i >> 7, k = i & 127;
        int n = min(base + r, N - 1);
        sInT[k * SROW + r] = (k < 64) ? g_agg[(size_t)n * 64 + k] * sInv[r]
                                      : g_node[(size_t)n * 128 + 64 + (k - 64)];
    }
    __syncthreads();
    int w = t >> 5, l = t & 31;
    int c0 = 32 * w + (l & 7) * 4, r0 = (l >> 3) * 8;
    ull acc[4][4];
    init_bias<4>(acc, b0, c0);
    gemmA(acc, W0, 128, 128, sInT, c0, r0);
    relu_store_hT(acc, sHT, c0, r0);
    __syncthreads();
    int c0b = 16 * w + (l & 3) * 4, r0b = (l >> 2) * 4;
    ull acc2[2][4];
    init_bias<2>(acc2, b1, c0b);
    gemmB(acc2, W1, 64, 128, sHT, c0b, r0b);
#pragma unroll
    for (int p = 0; p < 2; p++) {
        int rA = r0b + 2 * p, nA = base + rA;
#pragma unroll
        for (int c = 0; c < 4; c++) {
            int col = c0b + c;
            ull oldp = *reinterpret_cast<const ull*>(&sInT[(64 + col) * SROW + rA]);
            ull np = add2(oldp, acc2[p][c]);
            float a, b; upk2(np, a, b);
            if (nA < N)     g_node[(size_t)nA * 128 + 64 + col] = a;
            if (nA + 1 < N) g_node[(size_t)(nA + 1) * 128 + 64 + col] = b;
        }
    }
}

__global__ void __launch_bounds__(128)
k_decode(const float* __restrict__ W0, const float* __restrict__ b0,
         const float* __restrict__ W1, const float* __restrict__ b1,
         float* __restrict__ out, int N) {
    __shared__ float sInT[128 * SROW];
    __shared__ float sHT[128 * SROW];
    int t = threadIdx.x, base = blockIdx.x * 32;
    for (int i = t; i < 32 * 128; i += 128) {
        int r = i >> 7, k = i & 127;
        int n = min(base + r, N - 1);
        sInT[k * SROW + r] = g_node[(size_t)n * 128 + k];
    }
    __syncthreads();
    int w = t >> 5, l = t & 31;
    int c0 = 32 * w + (l & 7) * 4, r0 = (l >> 3) * 8;
    ull acc[4][4];
    init_bias<4>(acc, b0, c0);
    gemmA(acc, W0, 128, 128, sInT, c0, r0);
    relu_store_hT(acc, sHT, c0, r0);
    __syncthreads();
    if (t < 96) {
        int r = t / 3, c = t - 3 * (t / 3);
        float s = b1[c];
#pragma unroll 8
        for (int j = 0; j < 128; j++) s += sHT[j * SROW + r] * W1[j * 3 + c];
        int n = base + r;
        if (n < N) out[n * 3 + c] = s;
    }
}

// ---------------- launch ----------------
extern "C" void kernel_launch(void* const* d_in, const int* in_sizes, int n_in,
                              void* d_out, int out_size) {
    (void)n_in; (void)out_size;
    const int*   ei   = (const int*)d_in[0];
    const float* nf   = (const float*)d_in[1];
    const float* ef   = (const float*)d_in[2];
    const float* emb  = (const float*)d_in[3];
    const float* enW0 = (const float*)d_in[4],  *enb0 = (const float*)d_in[5];
    const float* enW1 = (const float*)d_in[6],  *enb1 = (const float*)d_in[7];
    const float* eeW0 = (const float*)d_in[8],  *eeb0 = (const float*)d_in[9];
    const float* eeW1 = (const float*)d_in[10], *eeb1 = (const float*)d_in[11];
    const float* ceW0 = (const float*)d_in[12], *ceb0 = (const float*)d_in[13];
    const float* ceW1 = (const float*)d_in[14], *ceb1 = (const float*)d_in[15];
    const float* cnW0 = (const float*)d_in[16], *cnb0 = (const float*)d_in[17];
    const float* cnW1 = (const float*)d_in[18], *cnb1 = (const float*)d_in[19];
    const float* dW0  = (const float*)d_in[20], *db0  = (const float*)d_in[21];
    const float* dW1  = (const float*)d_in[22], *db1  = (const float*)d_in[23];
    float* out = (float*)d_out;

    int N = in_sizes[1] / 32;
    int E = in_sizes[0] / 2;
    int nb = (N + 31) / 32;

    const int SM_CORE = (B1_OFF + 64) * 4;              // 170752
    const int SM_ENC  = (EA_OFF + 128 * 68) * 4;        // 74752
    cudaFuncSetAttribute(k_edge_core_mma, cudaFuncAttributeMaxDynamicSharedMemorySize, SM_CORE);
    cudaFuncSetAttribute(k_encode_edge_mma, cudaFuncAttributeMaxDynamicSharedMemorySize, SM_ENC);

    int prep_tot = 128 * 192 + 64 * 128 + 128 * 8 + 64 * 128;
    k_prep<<<(prep_tot + 255) / 256, 256>>>(ceW0, ceW1, eeW0, eeW1);
    k_zero_counts<<<(N + 255) / 256, 256>>>(N);
    k_counts<<<(E + 255) / 256, 256>>>(ei, E);
    k_encode_node<<<nb, 128>>>(nf, emb, enW0, enb0, enW1, enb1, N);

    int enc_b = (E + 128 * T_ENC - 1) / (128 * T_ENC);
    k_encode_edge_mma<<<enc_b, 256, SM_ENC>>>(ef, eeb0, eeb1 + 64, E);

    int core_b = (E + 128 * T_CORE - 1) / (128 * T_CORE);
    for (int s = 0; s < 3; s++) {
        k_zero_agg<<<(N * 64 + 255) / 256, 256>>>(N * 64);
        k_edge_core_mma<<<core_b, 256, SM_CORE>>>(ei, ceb0, ceb1, E);
        k_node_core<<<nb, 128>>>(cnW0, cnb0, cnW1, cnb1, N);
    }
    k_decode<<<nb, 128>>>(dW0, db0, dW1, db1, out, N);
}

// round 13
// speedup vs baseline: 1.0972x; 1.0972x over previous
#include <cuda_runtime.h>
#include <cstdint>

#define SROW 36
#define MAXN 50048
#define MAXE 800032
typedef unsigned long long ull;

__device__ float g_node[(size_t)MAXN * 128];
__device__ float g_edge_tail[(size_t)MAXE * 64];
__device__ float g_agg[(size_t)MAXN * 64];
__device__ float g_counts[MAXN];
__device__ float g_W0T[128 * 192];   // core_e_W0^T [n=128][k=192], tf32-rounded
__device__ float g_W1T[64 * 128];    // core_e_W1^T [n=64][k=128]
__device__ float g_eW0T[128 * 8];    // enc_e_W0^T  [n=128][k=8 pad]
__device__ float g_eW1T[64 * 128];   // enc_e_W1[:,64:]^T

// ---------------- tf32 mma.sync helpers ----------------
__device__ __forceinline__ uint32_t f2tf(float x) {
    uint32_t u; asm("cvt.rna.tf32.f32 %0, %1;" : "=r"(u) : "f"(x));
    return u;
}
#define MMA8(d, a0, a1, a2, a3, b0, b1)                                        \
    asm volatile(                                                              \
        "mma.sync.aligned.m16n8k8.row.col.f32.tf32.tf32.f32 "                  \
        "{%0,%1,%2,%3}, {%4,%5,%6,%7}, {%8,%9}, {%0,%1,%2,%3};"                \
        : "+f"((d)[0]), "+f"((d)[1]), "+f"((d)[2]), "+f"((d)[3])               \
        : "r"(a0), "r"(a1), "r"(a2), "r"(a3), "r"(b0), "r"(b1))

// ---------------- small kernels ----------------
__global__ void k_prep(const float* __restrict__ ceW0, const float* __restrict__ ceW1,
                       const float* __restrict__ eeW0, const float* __restrict__ eeW1) {
    int i = blockIdx.x * 256 + threadIdx.x;
    if (i < 128 * 192) { int n = i / 192, k = i % 192; g_W0T[i] = __uint_as_float(f2tf(ceW0[k * 128 + n])); }
    int j = i - 128 * 192;
    if (j >= 0 && j < 64 * 128) { int n = j / 128, k = j % 128; g_W1T[j] = __uint_as_float(f2tf(ceW1[k * 64 + n])); }
    int m = j - 64 * 128;
    if (m >= 0 && m < 128 * 8) { int n = m / 8, k = m % 8; g_eW0T[m] = (k < 3) ? __uint_as_float(f2tf(eeW0[k * 128 + n])) : 0.f; }
    int q = m - 128 * 8;
    if (q >= 0 && q < 64 * 128) { int n = q / 128, k = q % 128; g_eW1T[q] = __uint_as_float(f2tf(eeW1[k * 128 + 64 + n])); }
}
__global__ void k_zero_counts(int n) { int i = blockIdx.x*256+threadIdx.x; if (i < n) g_counts[i] = 0.f; }
__global__ void k_zero_agg(int n)    { int i = blockIdx.x*256+threadIdx.x; if (i < n) g_agg[i] = 0.f; }
__global__ void k_counts(const int* __restrict__ ei, int E) {
    int e = blockIdx.x*256+threadIdx.x;
    if (e < E) atomicAdd(&g_counts[ei[E + e]], 1.0f);
}

// ---------------------------------------------------------------------------
// core edge step, tensor (tf32 mma.sync), 512 threads = 2 x 128-row sub-tiles
// smem (floats): sW0[128][196]=25088 | sW1[64][132]=8448 | sA[256][68]=17408
//                | idx[512] | b0[128] | b1[64]
// ---------------------------------------------------------------------------
#define T_CORE 4
#define W1_OFF 25088
#define A_OFF  33536
#define IDX_OFF 50944
#define B0_OFF 51456
#define B1_OFF 51584
#define SM_CORE_F (B1_OFF + 64)
__global__ void __launch_bounds__(512, 1)
k_edge_core_mma(const int* __restrict__ ei, const float* __restrict__ b0g,
                const float* __restrict__ b1g, int E) {
    extern __shared__ float sm[];
    float* sW0 = sm;
    float* sW1 = sm + W1_OFF;
    float* sA  = sm + A_OFF;
    int*   sIdx = (int*)(sm + IDX_OFF);   // [0:256) dst, [256:512) src
    float* sB0 = sm + B0_OFF;
    float* sB1 = sm + B1_OFF;
    int t = threadIdx.x, w = t >> 5, lane = t & 31;
    int tg = lane & 3, lg = lane >> 2;
    int rb = 16 * w;                       // warp's 16-row band in sA (0..240)

    for (int i = t; i < 128 * 48; i += 512) {
        int n = i / 48, j = i % 48;
        *(float4*)(sW0 + n * 196 + j * 4) = *(const float4*)(g_W0T + n * 192 + j * 4);
    }
    for (int i = t; i < 64 * 32; i += 512) {
        int n = i / 32, j = i % 32;
        *(float4*)(sW1 + n * 132 + j * 4) = *(const float4*)(g_W1T + n * 128 + j * 4);
    }
    if (t < 128) sB0[t] = b0g[t];
    else if (t < 192) sB1[t - 128] = b1g[t - 128];
    __syncthreads();

    for (int tt = 0; tt < T_CORE; tt++) {
        int base = (blockIdx.x * T_CORE + tt) * 256;
        if (base >= E) break;
        __syncthreads();
        if (t < 256) {
            int e = min(base + t, E - 1);
            sIdx[t] = ei[E + e];
            sIdx[256 + t] = ei[e];
        }
        __syncthreads();

        float d1[16][4];
#pragma unroll
        for (int n0 = 0; n0 < 16; n0++)
#pragma unroll
            for (int c = 0; c < 4; c++) d1[n0][c] = 0.f;

        int row = t >> 1, half = t & 1;          // row 0..255 within block tile
        int er = min(base + row, E - 1);

        for (int ch = 0; ch < 3; ch++) {
            const float* p;
            if (ch == 0)      p = g_edge_tail + (size_t)er * 64;
            else if (ch == 1) p = g_node + (size_t)sIdx[row] * 128 + 64;
            else              p = g_node + (size_t)sIdx[256 + row] * 128 + 64;
            p += half * 32;
            float* dst = sA + row * 68 + half * 32;
#pragma unroll
            for (int j = 0; j < 8; j++) {
                float4 v = *(const float4*)(p + j * 4);
                *(float4*)(dst + j * 4) = make_float4(
                    __uint_as_float(f2tf(v.x)), __uint_as_float(f2tf(v.y)),
                    __uint_as_float(f2tf(v.z)), __uint_as_float(f2tf(v.w)));
            }
            __syncwarp();                         // warp's gather rows == its mma band
            for (int k0 = 0; k0 < 8; k0++) {
                int kb = k0 * 8 + tg;
                uint32_t a0 = __float_as_uint(sA[(rb + lg) * 68 + kb]);
                uint32_t a1 = __float_as_uint(sA[(rb + lg + 8) * 68 + kb]);
                uint32_t a2 = __float_as_uint(sA[(rb + lg) * 68 + kb + 4]);
                uint32_t a3 = __float_as_uint(sA[(rb + lg + 8) * 68 + kb + 4]);
                int kg = ch * 64 + k0 * 8 + tg;
#pragma unroll
                for (int n0 = 0; n0 < 16; n0++) {
                    uint32_t b0 = __float_as_uint(sW0[(n0 * 8 + lg) * 196 + kg]);
                    uint32_t b1 = __float_as_uint(sW0[(n0 * 8 + lg) * 196 + kg + 4]);
                    MMA8(d1[n0], a0, a1, a2, a3, b0, b1);
                }
            }
            __syncwarp();
        }

        float d2[8][4];
#pragma unroll
        for (int n0 = 0; n0 < 8; n0++)
#pragma unroll
            for (int c = 0; c < 4; c++) d2[n0][c] = 0.f;

        for (int nh = 0; nh < 2; nh++) {
#pragma unroll
            for (int q = 0; q < 8; q++) {
                int n0 = nh * 8 + q;
                int c0 = n0 * 8 + 2 * tg, cl = c0 - nh * 64;
                float ba = sB0[c0], bb = sB0[c0 + 1];
                float h0 = fmaxf(d1[n0][0] + ba, 0.f), h1 = fmaxf(d1[n0][1] + bb, 0.f);
                float h2 = fmaxf(d1[n0][2] + ba, 0.f), h3 = fmaxf(d1[n0][3] + bb, 0.f);
                *(float2*)(sA + (rb + lg) * 68 + cl) =
                    make_float2(__uint_as_float(f2tf(h0)), __uint_as_float(f2tf(h1)));
                *(float2*)(sA + (rb + lg + 8) * 68 + cl) =
                    make_float2(__uint_as_float(f2tf(h2)), __uint_as_float(f2tf(h3)));
            }
            __syncwarp();
            for (int k0 = 0; k0 < 8; k0++) {
                int kb = k0 * 8 + tg;
                uint32_t a0 = __float_as_uint(sA[(rb + lg) * 68 + kb]);
                uint32_t a1 = __float_as_uint(sA[(rb + lg + 8) * 68 + kb]);
                uint32_t a2 = __float_as_uint(sA[(rb + lg) * 68 + kb + 4]);
                uint32_t a3 = __float_as_uint(sA[(rb + lg + 8) * 68 + kb + 4]);
                int kg = nh * 64 + k0 * 8 + tg;
#pragma unroll
                for (int n0 = 0; n0 < 8; n0++) {
                    uint32_t b0 = __float_as_uint(sW1[(n0 * 8 + lg) * 132 + kg]);
                    uint32_t b1 = __float_as_uint(sW1[(n0 * 8 + lg) * 132 + kg + 4]);
                    MMA8(d2[n0], a0, a1, a2, a3, b0, b1);
                }
            }
            __syncwarp();
        }

        // epilogue (R11-proven): residual + bias, store tail, scalar atomics
        int r0 = rb + lg, r1 = r0 + 8;
#pragma unroll
        for (int n0 = 0; n0 < 8; n0++) {
            int c = n0 * 8 + 2 * tg;
            float ba = sB1[c], bb = sB1[c + 1];
            int e0 = base + r0;
            if (e0 < E) {
                float2 rv = *(const float2*)(g_edge_tail + (size_t)e0 * 64 + c);
                float x0 = d2[n0][0] + ba + rv.x, x1 = d2[n0][1] + bb + rv.y;
                *(float2*)(g_edge_tail + (size_t)e0 * 64 + c) = make_float2(x0, x1);
                float* pa = g_agg + (size_t)sIdx[r0] * 64 + c;
                atomicAdd(pa, x0); atomicAdd(pa + 1, x1);
            }
            int e1 = base + r1;
            if (e1 < E) {
                float2 rv = *(const float2*)(g_edge_tail + (size_t)e1 * 64 + c);
                float x0 = d2[n0][2] + ba + rv.x, x1 = d2[n0][3] + bb + rv.y;
                *(float2*)(g_edge_tail + (size_t)e1 * 64 + c) = make_float2(x0, x1);
                float* pa = g_agg + (size_t)sIdx[r1] * 64 + c;
                atomicAdd(pa, x0); atomicAdd(pa + 1, x1);
            }
        }
    }
}

// ---------------------------------------------------------------------------
// encode edge, tensor (unchanged from R11 WIN)
// ---------------------------------------------------------------------------
#define T_ENC 8
#define EW1_OFF 1536
#define EA_OFF  9984
__global__ void __launch_bounds__(256, 1)
k_encode_edge_mma(const float* __restrict__ ef, const float* __restrict__ b0g,
                  const float* __restrict__ b1g, int E) {
    extern __shared__ float sm[];
    float* sW0 = sm;
    float* sW1 = sm + EW1_OFF;
    float* sA  = sm + EA_OFF;
    int t = threadIdx.x, w = t >> 5, lane = t & 31;
    int tg = lane & 3, lg = lane >> 2, rb = 16 * w;

    for (int i = t; i < 128 * 2; i += 256) {
        int n = i / 2, j = i % 2;
        *(float4*)(sW0 + n * 12 + j * 4) = *(const float4*)(g_eW0T + n * 8 + j * 4);
    }
    for (int i = t; i < 64 * 32; i += 256) {
        int n = i / 32, j = i % 32;
        *(float4*)(sW1 + n * 132 + j * 4) = *(const float4*)(g_eW1T + n * 128 + j * 4);
    }
    __syncthreads();

    for (int tt = 0; tt < T_ENC; tt++) {
        int base = (blockIdx.x * T_ENC + tt) * 128;
        if (base >= E) break;
        int row = t >> 1, half = t & 1;
        int er = min(base + row, E - 1);
        {
            float* dst = sA + row * 68 + half * 4;
            if (half == 0) {
                *(float4*)dst = make_float4(
                    __uint_as_float(f2tf(ef[er * 3 + 0])),
                    __uint_as_float(f2tf(ef[er * 3 + 1])),
                    __uint_as_float(f2tf(ef[er * 3 + 2])), 0.f);
            } else {
                *(float4*)dst = make_float4(0.f, 0.f, 0.f, 0.f);
            }
        }
        __syncwarp();

        float d1[16][4];
#pragma unroll
        for (int n0 = 0; n0 < 16; n0++)
#pragma unroll
            for (int c = 0; c < 4; c++) d1[n0][c] = 0.f;
        {
            uint32_t a0 = __float_as_uint(sA[(rb + lg) * 68 + tg]);
            uint32_t a1 = __float_as_uint(sA[(rb + lg + 8) * 68 + tg]);
            uint32_t a2 = __float_as_uint(sA[(rb + lg) * 68 + tg + 4]);
            uint32_t a3 = __float_as_uint(sA[(rb + lg + 8) * 68 + tg + 4]);
#pragma unroll
            for (int n0 = 0; n0 < 16; n0++) {
                uint32_t b0 = __float_as_uint(sW0[(n0 * 8 + lg) * 12 + tg]);
                uint32_t b1 = __float_as_uint(sW0[(n0 * 8 + lg) * 12 + tg + 4]);
                MMA8(d1[n0], a0, a1, a2, a3, b0, b1);
            }
        }
        __syncwarp();

        float d2[8][4];
#pragma unroll
        for (int n0 = 0; n0 < 8; n0++)
#pragma unroll
            for (int c = 0; c < 4; c++) d2[n0][c] = 0.f;

        for (int nh = 0; nh < 2; nh++) {
#pragma unroll
            for (int q = 0; q < 8; q++) {
                int n0 = nh * 8 + q;
                int c0 = n0 * 8 + 2 * tg, cl = c0 - nh * 64;
                float ba = __ldg(b0g + c0), bb = __ldg(b0g + c0 + 1);
                float h0 = fmaxf(d1[n0][0] + ba, 0.f), h1 = fmaxf(d1[n0][1] + bb, 0.f);
                float h2 = fmaxf(d1[n0][2] + ba, 0.f), h3 = fmaxf(d1[n0][3] + bb, 0.f);
                *(float2*)(sA + (rb + lg) * 68 + cl) =
                    make_float2(__uint_as_float(f2tf(h0)), __uint_as_float(f2tf(h1)));
                *(float2*)(sA + (rb + lg + 8) * 68 + cl) =
                    make_float2(__uint_as_float(f2tf(h2)), __uint_as_float(f2tf(h3)));
            }
            __syncwarp();
            for (int k0 = 0; k0 < 8; k0++) {
                int kb = k0 * 8 + tg;
                uint32_t a0 = __float_as_uint(sA[(rb + lg) * 68 + kb]);
                uint32_t a1 = __float_as_uint(sA[(rb + lg + 8) * 68 + kb]);
                uint32_t a2 = __float_as_uint(sA[(rb + lg) * 68 + kb + 4]);
                uint32_t a3 = __float_as_uint(sA[(rb + lg + 8) * 68 + kb + 4]);
                int kg = nh * 64 + k0 * 8 + tg;
#pragma unroll
                for (int n0 = 0; n0 < 8; n0++) {
                    uint32_t b0 = __float_as_uint(sW1[(n0 * 8 + lg) * 132 + kg]);
                    uint32_t b1 = __float_as_uint(sW1[(n0 * 8 + lg) * 132 + kg + 4]);
                    MMA8(d2[n0], a0, a1, a2, a3, b0, b1);
                }
            }
            __syncwarp();
        }

        int r0 = rb + lg, r1 = r0 + 8;
#pragma unroll
        for (int n0 = 0; n0 < 8; n0++) {
            int c = n0 * 8 + 2 * tg;
            float ba = __ldg(b1g + c), bb = __ldg(b1g + c + 1);
            int e0 = base + r0;
            if (e0 < E)
                *(float2*)(g_edge_tail + (size_t)e0 * 64 + c) =
                    make_float2(d2[n0][0] + ba, d2[n0][1] + bb);
            int e1 = base + r1;
            if (e1 < E)
                *(float2*)(g_edge_tail + (size_t)e1 * 64 + c) =
                    make_float2(d2[n0][2] + ba, d2[n0][3] + bb);
        }
        __syncwarp();
    }
}

// ---------------- scalar fp32 node-side ----------------
__device__ __forceinline__ ull pk2(float a, float b) { ull r; asm("mov.b64 %0, {%1, %2};" : "=l"(r) : "f"(a), "f"(b)); return r; }
__device__ __forceinline__ void upk2(ull v, float &a, float &b) { asm("mov.b64 {%0, %1}, %2;" : "=f"(a), "=f"(b) : "l"(v)); }
__device__ __forceinline__ void fma2(ull &d, ull a, ull b) { asm("fma.rn.f32x2 %0, %1, %2, %3;" : "=l"(d) : "l"(a), "l"(b), "l"(d)); }
__device__ __forceinline__ ull add2(ull a, ull b) { ull r; asm("add.rn.f32x2 %0, %1, %2;" : "=l"(r) : "l"(a), "l"(b)); return r; }
__device__ __forceinline__ void gemmA(ull (&acc)[4][4], const float* __restrict__ W, int ld, int K,
                                      const float* sInT, int c0, int r0) {
#pragma unroll 4
    for (int k = 0; k < K; k++) {
        float4 w = __ldg(reinterpret_cast<const float4*>(W + (size_t)k * ld + c0));
        ull w0 = pk2(w.x, w.x), w1 = pk2(w.y, w.y), w2 = pk2(w.z, w.z), w3 = pk2(w.w, w.w);
        const float* row = sInT + k * SROW + r0;
        ulonglong2 xa = *reinterpret_cast<const ulonglong2*>(row);
        ulonglong2 xb = *reinterpret_cast<const ulonglong2*>(row + 4);
        fma2(acc[0][0], xa.x, w0); fma2(acc[0][1], xa.x, w1); fma2(acc[0][2], xa.x, w2); fma2(acc[0][3], xa.x, w3);
        fma2(acc[1][0], xa.y, w0); fma2(acc[1][1], xa.y, w1); fma2(acc[1][2], xa.y, w2); fma2(acc[1][3], xa.y, w3);
        fma2(acc[2][0], xb.x, w0); fma2(acc[2][1], xb.x, w1); fma2(acc[2][2], xb.x, w2); fma2(acc[2][3], xb.x, w3);
        fma2(acc[3][0], xb.y, w0); fma2(acc[3][1], xb.y, w1); fma2(acc[3][2], xb.y, w2); fma2(acc[3][3], xb.y, w3);
    }
}
__device__ __forceinline__ void gemmB(ull (&acc)[2][4], const float* __restrict__ W, int ld, int K,
                                      const float* sInT, int c0, int r0) {
#pragma unroll 4
    for (int k = 0; k < K; k++) {
        float4 w = __ldg(reinterpret_cast<const float4*>(W + (size_t)k * ld + c0));
        ull w0 = pk2(w.x, w.x), w1 = pk2(w.y, w.y), w2 = pk2(w.z, w.z), w3 = pk2(w.w, w.w);
        ulonglong2 xa = *reinterpret_cast<const ulonglong2*>(sInT + k * SROW + r0);
        fma2(acc[0][0], xa.x, w0); fma2(acc[0][1], xa.x, w1); fma2(acc[0][2], xa.x, w2); fma2(acc[0][3], xa.x, w3);
        fma2(acc[1][0], xa.y, w0); fma2(acc[1][1], xa.y, w1); fma2(acc[1][2], xa.y, w2); fma2(acc[1][3], xa.y, w3);
    }
}
template <int NP>
__device__ __forceinline__ void init_bias(ull (&acc)[NP][4], const float* __restrict__ b, int c0) {
#pragma unroll
    for (int c = 0; c < 4; c++) {
        float bv = b[c0 + c]; ull bb = pk2(bv, bv);
#pragma unroll
        for (int p = 0; p < NP; p++) acc[p][c] = bb;
    }
}
__device__ __forceinline__ void relu_store_hT(ull (&acc)[4][4], float* sHT, int c0, int r0) {
#pragma unroll
    for (int p = 0; p < 4; p++)
#pragma unroll
        for (int c = 0; c < 4; c++) {
            float a, b; upk2(acc[p][c], a, b);
            *reinterpret_cast<float2*>(&sHT[(c0 + c) * SROW + r0 + 2 * p]) =
                make_float2(fmaxf(a, 0.f), fmaxf(b, 0.f));
        }
}

__global__ void __launch_bounds__(128)
k_encode_node(const float* __restrict__ nf, const float* __restrict__ emb,
              const float* __restrict__ W0, const float* __restrict__ b0,
              const float* __restrict__ W1, const float* __restrict__ b1, int N) {
    __shared__ float sInT[47 * SROW];
    __shared__ float sHT[128 * SROW];
    __shared__ int sPT[32];
    int t = threadIdx.x, base = blockIdx.x * 32;
    if (t < 32) { int n = min(base + t, N - 1); sPT[t] = (int)(nf[n * 32 + 31] + 0.5f); }
    __syncthreads();
    for (int i = t; i < 32 * 47; i += 128) {
        int r = i / 47, k = i - r * 47;
        int n = min(base + r, N - 1);
        sInT[k * SROW + r] = (k < 31) ? nf[n * 32 + k] : emb[sPT[r] * 16 + (k - 31)];
    }
    __syncthreads();
    int w = t >> 5, l = t & 31;
    int c0 = 32 * w + (l & 7) * 4, r0 = (l >> 3) * 8;
    ull acc[4][4];
    init_bias<4>(acc, b0, c0);
    gemmA(acc, W0, 128, 47, sInT, c0, r0);
    relu_store_hT(acc, sHT, c0, r0);
    __syncthreads();
    ull acc2[4][4];
    init_bias<4>(acc2, b1, c0);
    gemmA(acc2, W1, 128, 128, sHT, c0, r0);
#pragma unroll
    for (int p = 0; p < 4; p++)
#pragma unroll
        for (int c = 0; c < 4; c++) {
            float a, b; upk2(acc2[p][c], a, b);
            int rA = base + r0 + 2 * p;
            if (rA < N)     g_node[(size_t)rA * 128 + c0 + c] = a;
            if (rA + 1 < N) g_node[(size_t)(rA + 1) * 128 + c0 + c] = b;
        }
}

__global__ void __launch_bounds__(128)
k_node_core(const float* __restrict__ W0, const float* __restrict__ b0,
            const float* __restrict__ W1, const float* __restrict__ b1, int N) {
    __shared__ float sInT[128 * SROW];
    __shared__ float sHT[128 * SROW];
    __shared__ float sInv[32];
    int t = threadIdx.x, base = blockIdx.x * 32;
    if (t < 32) { int n = min(base + t, N - 1); sInv[t] = 1.0f / fmaxf(g_counts[n], 1.0f); }
    __syncthreads();
    for (int i = t; i < 32 * 128; i += 128) {
        int r = i >> 7, k = i & 127;
        int n = min(base + r, N - 1);
        sInT[k * SROW + r] = (k < 64) ? g_agg[(size_t)n * 64 + k] * sInv[r]
                                      : g_node[(size_t)n * 128 + 64 + (k - 64)];
    }
    __syncthreads();
    int w = t >> 5, l = t & 31;
    int c0 = 32 * w + (l & 7) * 4, r0 = (l >> 3) * 8;
    ull acc[4][4];
    init_bias<4>(acc, b0, c0);
    gemmA(acc, W0, 128, 128, sInT, c0, r0);
    relu_store_hT(acc, sHT, c0, r0);
    __syncthreads();
    int c0b = 16 * w + (l & 3) * 4, r0b = (l >> 2) * 4;
    ull acc2[2][4];
    init_bias<2>(acc2, b1, c0b);
    gemmB(acc2, W1, 64, 128, sHT, c0b, r0b);
#pragma unroll
    for (int p = 0; p < 2; p++) {
        int rA = r0b + 2 * p, nA = base + rA;
#pragma unroll
        for (int c = 0; c < 4; c++) {
            int col = c0b + c;
            ull oldp = *reinterpret_cast<const ull*>(&sInT[(64 + col) * SROW + rA]);
            ull np = add2(oldp, acc2[p][c]);
            float a, b; upk2(np, a, b);
            if (nA < N)     g_node[(size_t)nA * 128 + 64 + col] = a;
            if (nA + 1 < N) g_node[(size_t)(nA + 1) * 128 + 64 + col] = b;
        }
    }
}

__global__ void __launch_bounds__(128)
k_decode(const float* __restrict__ W0, const float* __restrict__ b0,
         const float* __restrict__ W1, const float* __restrict__ b1,
         float* __restrict__ out, int N) {
    __shared__ float sInT[128 * SROW];
    __shared__ float sHT[128 * SROW];
    int t = threadIdx.x, base = blockIdx.x * 32;
    for (int i = t; i < 32 * 128; i += 128) {
        int r = i >> 7, k = i & 127;
        int n = min(base + r, N - 1);
        sInT[k * SROW + r] = g_node[(size_t)n * 128 + k];
    }
    __syncthreads();
    int w = t >> 5, l = t & 31;
    int c0 = 32 * w + (l & 7) * 4, r0 = (l >> 3) * 8;
    ull acc[4][4];
    init_bias<4>(acc, b0, c0);
    gemmA(acc, W0, 128, 128, sInT, c0, r0);
    relu_store_hT(acc, sHT, c0, r0);
    __syncthreads();
    if (t < 96) {
        int r = t / 3, c = t - 3 * (t / 3);
        float s = b1[c];
#pragma unroll 8
        for (int j = 0; j < 128; j++) s += sHT[j * SROW + r] * W1[j * 3 + c];
        int n = base + r;
        if (n < N) out[n * 3 + c] = s;
    }
}

// ---------------- launch ----------------
extern "C" void kernel_launch(void* const* d_in, const int* in_sizes, int n_in,
                              void* d_out, int out_size) {
    (void)n_in; (void)out_size;
    const int*   ei   = (const int*)d_in[0];
    const float* nf   = (const float*)d_in[1];
    const float* ef   = (const float*)d_in[2];
    const float* emb  = (const float*)d_in[3];
    const float* enW0 = (const float*)d_in[4],  *enb0 = (const float*)d_in[5];
    const float* enW1 = (const float*)d_in[6],  *enb1 = (const float*)d_in[7];
    const float* eeW0 = (const float*)d_in[8],  *eeb0 = (const float*)d_in[9];
    const float* eeW1 = (const float*)d_in[10], *eeb1 = (const float*)d_in[11];
    const float* ceW0 = (const float*)d_in[12], *ceb0 = (const float*)d_in[13];
    const float* ceW1 = (const float*)d_in[14], *ceb1 = (const float*)d_in[15];
    const float* cnW0 = (const float*)d_in[16], *cnb0 = (const float*)d_in[17];
    const float* cnW1 = (const float*)d_in[18], *cnb1 = (const float*)d_in[19];
    const float* dW0  = (const float*)d_in[20], *db0  = (const float*)d_in[21];
    const float* dW1  = (const float*)d_in[22], *db1  = (const float*)d_in[23];
    float* out = (float*)d_out;

    int N = in_sizes[1] / 32;
    int E = in_sizes[0] / 2;
    int nb = (N + 31) / 32;

    const int SM_CORE = SM_CORE_F * 4;                  // 206592 bytes
    const int SM_ENC  = (EA_OFF + 128 * 68) * 4;        // 74752
    cudaFuncSetAttribute(k_edge_core_mma, cudaFuncAttributeMaxDynamicSharedMemorySize, SM_CORE);
    cudaFuncSetAttribute(k_encode_edge_mma, cudaFuncAttributeMaxDynamicSharedMemorySize, SM_ENC);

    int prep_tot = 128 * 192 + 64 * 128 + 128 * 8 + 64 * 128;
    k_prep<<<(prep_tot + 255) / 256, 256>>>(ceW0, ceW1, eeW0, eeW1);
    k_zero_counts<<<(N + 255) / 256, 256>>>(N);
    k_counts<<<(E + 255) / 256, 256>>>(ei, E);
    k_encode_node<<<nb, 128>>>(nf, emb, enW0, enb0, enW1, enb1, N);

    int enc_b = (E + 128 * T_ENC - 1) / (128 * T_ENC);
    k_encode_edge_mma<<<enc_b, 256, SM_ENC>>>(ef, eeb0, eeb1 + 64, E);

    int core_b = (E + 256 * T_CORE - 1) / (256 * T_CORE);
    for (int s = 0; s < 3; s++) {
        k_zero_agg<<<(N * 64 + 255) / 256, 256>>>(N * 64);
        k_edge_core_mma<<<core_b, 512, SM_CORE>>>(ei, ceb0, ceb1, E);
        k_node_core<<<nb, 128>>>(cnW0, cnb0, cnW1, cnb1, N);
    }
    k_decode<<<nb, 128>>>(dW0, db0, dW1, db1, out, N);
}

// round 14
// speedup vs baseline: 1.5364x; 1.4003x over previous
#include <cuda_runtime.h>
#include <cuda_bf16.h>
#include <cstdint>

#define SROW 36
#define MAXN 50048
#define MAXE 800032
typedef unsigned long long ull;

__device__ float g_node[(size_t)MAXN * 128];
__device__ float g_edge_tail[(size_t)MAXE * 64];
__device__ float g_agg[(size_t)MAXN * 64];
__device__ float g_counts[MAXN];
__device__ uint32_t g_W0Tb[128 * 96];   // core_e_W0^T bf16x2 [n=128][kpair=96]
__device__ uint32_t g_W1Tb[64 * 64];    // core_e_W1^T bf16x2 [n=64][kpair=64]
__device__ float g_eW0T[128 * 8];       // enc_e_W0^T tf32 [n=128][k=8 pad]
__device__ float g_eW1T[64 * 128];      // enc_e_W1[:,64:]^T tf32

// ---------------- helpers ----------------
__device__ __forceinline__ uint32_t f2tf(float x) {
    uint32_t u; asm("cvt.rna.tf32.f32 %0, %1;" : "=r"(u) : "f"(x));
    return u;
}
__device__ __forceinline__ uint32_t pkbf(float lo, float hi) {
    uint32_t r; asm("cvt.rn.bf16x2.f32 %0, %1, %2;" : "=r"(r) : "f"(hi), "f"(lo));
    return r;   // lo in low 16 bits
}
#define MMA8(d, a0, a1, a2, a3, b0, b1)                                        \
    asm volatile(                                                              \
        "mma.sync.aligned.m16n8k8.row.col.f32.tf32.tf32.f32 "                  \
        "{%0,%1,%2,%3}, {%4,%5,%6,%7}, {%8,%9}, {%0,%1,%2,%3};"                \
        : "+f"((d)[0]), "+f"((d)[1]), "+f"((d)[2]), "+f"((d)[3])               \
        : "r"(a0), "r"(a1), "r"(a2), "r"(a3), "r"(b0), "r"(b1))
#define MMA16(d, a0, a1, a2, a3, b0, b1)                                       \
    asm volatile(                                                              \
        "mma.sync.aligned.m16n8k16.row.col.f32.bf16.bf16.f32 "                 \
        "{%0,%1,%2,%3}, {%4,%5,%6,%7}, {%8,%9}, {%0,%1,%2,%3};"                \
        : "+f"((d)[0]), "+f"((d)[1]), "+f"((d)[2]), "+f"((d)[3])               \
        : "r"(a0), "r"(a1), "r"(a2), "r"(a3), "r"(b0), "r"(b1))
#define BAR128(id) asm volatile("bar.sync %0, %1;" :: "r"(id), "r"(128) : "memory")

// ---------------- small kernels ----------------
__global__ void k_prep(const float* __restrict__ ceW0, const float* __restrict__ ceW1,
                       const float* __restrict__ eeW0, const float* __restrict__ eeW1) {
    int i = blockIdx.x * 256 + threadIdx.x;
    if (i < 128 * 96) {
        int n = i / 96, j = i % 96;
        g_W0Tb[i] = pkbf(ceW0[(2 * j) * 128 + n], ceW0[(2 * j + 1) * 128 + n]);
    }
    int j2 = i - 128 * 96;
    if (j2 >= 0 && j2 < 64 * 64) {
        int n = j2 / 64, j = j2 % 64;
        g_W1Tb[j2] = pkbf(ceW1[(2 * j) * 64 + n], ceW1[(2 * j + 1) * 64 + n]);
    }
    int m = j2 - 64 * 64;
    if (m >= 0 && m < 128 * 8) { int n = m / 8, k = m % 8; g_eW0T[m] = (k < 3) ? __uint_as_float(f2tf(eeW0[k * 128 + n])) : 0.f; }
    int q = m - 128 * 8;
    if (q >= 0 && q < 64 * 128) { int n = q / 128, k = q % 128; g_eW1T[q] = __uint_as_float(f2tf(eeW1[k * 128 + 64 + n])); }
}
__global__ void k_zero_counts(int n) { int i = blockIdx.x*256+threadIdx.x; if (i < n) g_counts[i] = 0.f; }
__global__ void k_zero_agg(int n)    { int i = blockIdx.x*256+threadIdx.x; if (i < n) g_agg[i] = 0.f; }
__global__ void k_counts(const int* __restrict__ ei, int E) {
    int e = blockIdx.x*256+threadIdx.x;
    if (e < E) atomicAdd(&g_counts[ei[E + e]], 1.0f);
}

// ---------------------------------------------------------------------------
// core edge step, bf16 mma.m16n8k16, 256 threads = 2(m) x 4(n) warp grid
// smem u32: sW0[128][100] | sW1[64][68] | sA[128][100] | idx[256] | b0 | b1
// ---------------------------------------------------------------------------
#define T_CORE 4
#define CW1_OFF 12800
#define CA_OFF  17152
#define CIDX_OFF 29952
#define CB0_OFF 30208
#define CB1_OFF 30336
#define CSM_U32 30400
__global__ void __launch_bounds__(256, 1)
k_edge_core_mma(const int* __restrict__ ei, const float* __restrict__ b0g,
                const float* __restrict__ b1g, int E) {
    extern __shared__ uint32_t smu[];
    uint32_t* sW0 = smu;
    uint32_t* sW1 = smu + CW1_OFF;
    uint32_t* sA  = smu + CA_OFF;
    int*   sIdx = (int*)(smu + CIDX_OFF);     // [0:128) dst, [128:256) src
    float* sB0 = (float*)(smu + CB0_OFF);
    float* sB1 = (float*)(smu + CB1_OFF);
    int t = threadIdx.x, w = t >> 5, lane = t & 31;
    int tg = lane & 3, lg = lane >> 2;
    int wm = w >> 2, wn = w & 3;
    int RB = wm * 64, NB = wn * 32, NB2 = wn * 16;
    int rsub = lane >> 3, seg = lane & 7;     // gather mapping
    int GR = 16 * w;

    for (int i = t; i < 128 * 24; i += 256) {
        int n = i / 24, j = i % 24;
        *(uint4*)(sW0 + n * 100 + j * 4) = *(const uint4*)(g_W0Tb + n * 96 + j * 4);
    }
    for (int i = t; i < 64 * 16; i += 256) {
        int n = i / 16, j = i % 16;
        *(uint4*)(sW1 + n * 68 + j * 4) = *(const uint4*)(g_W1Tb + n * 64 + j * 4);
    }
    if (t < 128) sB0[t] = b0g[t];
    else if (t < 192) sB1[t - 128] = b1g[t - 128];
    __syncthreads();

    for (int tt = 0; tt < T_CORE; tt++) {
        int base = (blockIdx.x * T_CORE + tt) * 128;
        if (base >= E) break;
        __syncthreads();                       // prior tile done with sIdx/sA
        if (t < 128) {
            int e = min(base + t, E - 1);
            sIdx[t] = ei[E + e];
            sIdx[128 + t] = ei[e];
        }
        __syncthreads();

        // gather: warp w fills rows GR..GR+15 (bf16-packed), coalesced segs
#pragma unroll
        for (int it = 0; it < 4; it++) {
            int row = GR + it * 4 + rsub;
            int er = min(base + row, E - 1);
            const float* p0 = g_edge_tail + (size_t)er * 64;
            const float* p1 = g_node + (size_t)sIdx[row] * 128 + 64;
            const float* p2 = g_node + (size_t)sIdx[128 + row] * 128 + 64;
#pragma unroll
            for (int ch = 0; ch < 3; ch++) {
                const float* p = (ch == 0) ? p0 : (ch == 1) ? p1 : p2;
                float4 v0 = *(const float4*)(p + seg * 8);
                float4 v1 = *(const float4*)(p + seg * 8 + 4);
                uint4 u;
                u.x = pkbf(v0.x, v0.y); u.y = pkbf(v0.z, v0.w);
                u.z = pkbf(v1.x, v1.y); u.w = pkbf(v1.z, v1.w);
                *(uint4*)(sA + row * 100 + ch * 32 + seg * 4) = u;
            }
        }
        BAR128(1 + wm);

        // layer 1: [128x192] @ W0 -> warp computes 64 rows x 32 cols
        float d1[4][4][4];
#pragma unroll
        for (int m = 0; m < 4; m++)
#pragma unroll
            for (int n0 = 0; n0 < 4; n0++)
#pragma unroll
                for (int c = 0; c < 4; c++) d1[m][n0][c] = 0.f;

        for (int ks = 0; ks < 12; ks++) {
            uint32_t bf0[4], bf1[4];
#pragma unroll
            for (int n0 = 0; n0 < 4; n0++) {
                const uint32_t* bp = sW0 + (NB + n0 * 8 + lg) * 100 + ks * 8 + tg;
                bf0[n0] = bp[0]; bf1[n0] = bp[4];
            }
#pragma unroll
            for (int m = 0; m < 4; m++) {
                const uint32_t* ap = sA + (RB + m * 16 + lg) * 100 + ks * 8 + tg;
                uint32_t a0 = ap[0], a2 = ap[4], a1 = ap[800], a3 = ap[804];
#pragma unroll
                for (int n0 = 0; n0 < 4; n0++)
                    MMA16(d1[m][n0], a0, a1, a2, a3, bf0[n0], bf1[n0]);
            }
        }
        BAR128(1 + wm);

        // h = relu(d1 + b0) -> sA (bf16, u32 cols 0..63)
#pragma unroll
        for (int m = 0; m < 4; m++)
#pragma unroll
            for (int n0 = 0; n0 < 4; n0++) {
                int cb = NB + n0 * 8 + 2 * tg;
                float ba = sB0[cb], bb = sB0[cb + 1];
                float h0 = fmaxf(d1[m][n0][0] + ba, 0.f), h1 = fmaxf(d1[m][n0][1] + bb, 0.f);
                float h2 = fmaxf(d1[m][n0][2] + ba, 0.f), h3 = fmaxf(d1[m][n0][3] + bb, 0.f);
                int r = RB + m * 16 + lg;
                sA[r * 100 + (cb >> 1)] = pkbf(h0, h1);
                sA[(r + 8) * 100 + (cb >> 1)] = pkbf(h2, h3);
            }
        BAR128(1 + wm);

        // layer 2: h[128x128] @ W1 -> warp computes 64 rows x 16 cols
        float d2[4][2][4];
#pragma unroll
        for (int m = 0; m < 4; m++)
#pragma unroll
            for (int n0 = 0; n0 < 2; n0++)
#pragma unroll
                for (int c = 0; c < 4; c++) d2[m][n0][c] = 0.f;

        for (int ks = 0; ks < 8; ks++) {
            uint32_t bf0[2], bf1[2];
#pragma unroll
            for (int n0 = 0; n0 < 2; n0++) {
                const uint32_t* bp = sW1 + (NB2 + n0 * 8 + lg) * 68 + ks * 8 + tg;
                bf0[n0] = bp[0]; bf1[n0] = bp[4];
            }
#pragma unroll
            for (int m = 0; m < 4; m++) {
                const uint32_t* ap = sA + (RB + m * 16 + lg) * 100 + ks * 8 + tg;
                uint32_t a0 = ap[0], a2 = ap[4], a1 = ap[800], a3 = ap[804];
#pragma unroll
                for (int n0 = 0; n0 < 2; n0++)
                    MMA16(d2[m][n0], a0, a1, a2, a3, bf0[n0], bf1[n0]);
            }
        }

        // epilogue: tail += d2 + b1 ; store ; atomicAdd agg[dst]
#pragma unroll
        for (int m = 0; m < 4; m++)
#pragma unroll
            for (int n0 = 0; n0 < 2; n0++) {
                int cb = NB2 + n0 * 8 + 2 * tg;
                float ba = sB1[cb], bb = sB1[cb + 1];
                int r0 = RB + m * 16 + lg;
                int e0 = base + r0;
                if (e0 < E) {
                    float2 rv = *(const float2*)(g_edge_tail + (size_t)e0 * 64 + cb);
                    float x0 = d2[m][n0][0] + ba + rv.x, x1 = d2[m][n0][1] + bb + rv.y;
                    *(float2*)(g_edge_tail + (size_t)e0 * 64 + cb) = make_float2(x0, x1);
                    float* pa = g_agg + (size_t)sIdx[r0] * 64 + cb;
                    atomicAdd(pa, x0); atomicAdd(pa + 1, x1);
                }
                int r1 = r0 + 8, e1 = base + r1;
                if (e1 < E) {
                    float2 rv = *(const float2*)(g_edge_tail + (size_t)e1 * 64 + cb);
                    float x0 = d2[m][n0][2] + ba + rv.x, x1 = d2[m][n0][3] + bb + rv.y;
                    *(float2*)(g_edge_tail + (size_t)e1 * 64 + cb) = make_float2(x0, x1);
                    float* pa = g_agg + (size_t)sIdx[r1] * 64 + cb;
                    atomicAdd(pa, x0); atomicAdd(pa + 1, x1);
                }
            }
    }
}

// ---------------------------------------------------------------------------
// encode edge, tensor tf32 (unchanged R11 WIN)
// ---------------------------------------------------------------------------
#define T_ENC 8
#define EW1_OFF 1536
#define EA_OFF  9984
__global__ void __launch_bounds__(256, 1)
k_encode_edge_mma(const float* __restrict__ ef, const float* __restrict__ b0g,
                  const float* __restrict__ b1g, int E) {
    extern __shared__ float sm[];
    float* sW0 = sm;
    float* sW1 = sm + EW1_OFF;
    float* sA  = sm + EA_OFF;
    int t = threadIdx.x, w = t >> 5, lane = t & 31;
    int tg = lane & 3, lg = lane >> 2, rb = 16 * w;

    for (int i = t; i < 128 * 2; i += 256) {
        int n = i / 2, j = i % 2;
        *(float4*)(sW0 + n * 12 + j * 4) = *(const float4*)(g_eW0T + n * 8 + j * 4);
    }
    for (int i = t; i < 64 * 32; i += 256) {
        int n = i / 32, j = i % 32;
        *(float4*)(sW1 + n * 132 + j * 4) = *(const float4*)(g_eW1T + n * 128 + j * 4);
    }
    __syncthreads();

    for (int tt = 0; tt < T_ENC; tt++) {
        int base = (blockIdx.x * T_ENC + tt) * 128;
        if (base >= E) break;
        int row = t >> 1, half = t & 1;
        int er = min(base + row, E - 1);
        {
            float* dst = sA + row * 68 + half * 4;
            if (half == 0) {
                *(float4*)dst = make_float4(
                    __uint_as_float(f2tf(ef[er * 3 + 0])),
                    __uint_as_float(f2tf(ef[er * 3 + 1])),
                    __uint_as_float(f2tf(ef[er * 3 + 2])), 0.f);
            } else {
                *(float4*)dst = make_float4(0.f, 0.f, 0.f, 0.f);
            }
        }
        __syncwarp();

        float d1[16][4];
#pragma unroll
        for (int n0 = 0; n0 < 16; n0++)
#pragma unroll
            for (int c = 0; c < 4; c++) d1[n0][c] = 0.f;
        {
            uint32_t a0 = __float_as_uint(sA[(rb + lg) * 68 + tg]);
            uint32_t a1 = __float_as_uint(sA[(rb + lg + 8) * 68 + tg]);
            uint32_t a2 = __float_as_uint(sA[(rb + lg) * 68 + tg + 4]);
            uint32_t a3 = __float_as_uint(sA[(rb + lg + 8) * 68 + tg + 4]);
#pragma unroll
            for (int n0 = 0; n0 < 16; n0++) {
                uint32_t b0 = __float_as_uint(sW0[(n0 * 8 + lg) * 12 + tg]);
                uint32_t b1 = __float_as_uint(sW0[(n0 * 8 + lg) * 12 + tg + 4]);
                MMA8(d1[n0], a0, a1, a2, a3, b0, b1);
            }
        }
        __syncwarp();

        float d2[8][4];
#pragma unroll
        for (int n0 = 0; n0 < 8; n0++)
#pragma unroll
            for (int c = 0; c < 4; c++) d2[n0][c] = 0.f;

        for (int nh = 0; nh < 2; nh++) {
#pragma unroll
            for (int q = 0; q < 8; q++) {
                int n0 = nh * 8 + q;
                int c0 = n0 * 8 + 2 * tg, cl = c0 - nh * 64;
                float ba = __ldg(b0g + c0), bb = __ldg(b0g + c0 + 1);
                float h0 = fmaxf(d1[n0][0] + ba, 0.f), h1 = fmaxf(d1[n0][1] + bb, 0.f);
                float h2 = fmaxf(d1[n0][2] + ba, 0.f), h3 = fmaxf(d1[n0][3] + bb, 0.f);
                *(float2*)(sA + (rb + lg) * 68 + cl) =
                    make_float2(__uint_as_float(f2tf(h0)), __uint_as_float(f2tf(h1)));
                *(float2*)(sA + (rb + lg + 8) * 68 + cl) =
                    make_float2(__uint_as_float(f2tf(h2)), __uint_as_float(f2tf(h3)));
            }
            __syncwarp();
            for (int k0 = 0; k0 < 8; k0++) {
                int kb = k0 * 8 + tg;
                uint32_t a0 = __float_as_uint(sA[(rb + lg) * 68 + kb]);
                uint32_t a1 = __float_as_uint(sA[(rb + lg + 8) * 68 + kb]);
                uint32_t a2 = __float_as_uint(sA[(rb + lg) * 68 + kb + 4]);
                uint32_t a3 = __float_as_uint(sA[(rb + lg + 8) * 68 + kb + 4]);
                int kg = nh * 64 + k0 * 8 + tg;
#pragma unroll
                for (int n0 = 0; n0 < 8; n0++) {
                    uint32_t b0 = __float_as_uint(sW1[(n0 * 8 + lg) * 132 + kg]);
                    uint32_t b1 = __float_as_uint(sW1[(n0 * 8 + lg) * 132 + kg + 4]);
                    MMA8(d2[n0], a0, a1, a2, a3, b0, b1);
                }
            }
            __syncwarp();
        }

        int r0 = rb + lg, r1 = r0 + 8;
#pragma unroll
        for (int n0 = 0; n0 < 8; n0++) {
            int c = n0 * 8 + 2 * tg;
            float ba = __ldg(b1g + c), bb = __ldg(b1g + c + 1);
            int e0 = base + r0;
            if (e0 < E)
                *(float2*)(g_edge_tail + (size_t)e0 * 64 + c) =
                    make_float2(d2[n0][0] + ba, d2[n0][1] + bb);
            int e1 = base + r1;
            if (e1 < E)
                *(float2*)(g_edge_tail + (size_t)e1 * 64 + c) =
                    make_float2(d2[n0][2] + ba, d2[n0][3] + bb);
        }
        __syncwarp();
    }
}

// ---------------- scalar fp32 node-side (unchanged) ----------------
__device__ __forceinline__ ull pk2(float a, float b) { ull r; asm("mov.b64 %0, {%1, %2};" : "=l"(r) : "f"(a), "f"(b)); return r; }
__device__ __forceinline__ void upk2(ull v, float &a, float &b) { asm("mov.b64 {%0, %1}, %2;" : "=f"(a), "=f"(b) : "l"(v)); }
__device__ __forceinline__ void fma2(ull &d, ull a, ull b) { asm("fma.rn.f32x2 %0, %1, %2, %3;" : "=l"(d) : "l"(a), "l"(b), "l"(d)); }
__device__ __forceinline__ ull add2(ull a, ull b) { ull r; asm("add.rn.f32x2 %0, %1, %2;" : "=l"(r) : "l"(a), "l"(b)); return r; }
__device__ __forceinline__ void gemmA(ull (&acc)[4][4], const float* __restrict__ W, int ld, int K,
                                      const float* sInT, int c0, int r0) {
#pragma unroll 4
    for (int k = 0; k < K; k++) {
        float4 w = __ldg(reinterpret_cast<const float4*>(W + (size_t)k * ld + c0));
        ull w0 = pk2(w.x, w.x), w1 = pk2(w.y, w.y), w2 = pk2(w.z, w.z), w3 = pk2(w.w, w.w);
        const float* row = sInT + k * SROW + r0;
        ulonglong2 xa = *reinterpret_cast<const ulonglong2*>(row);
        ulonglong2 xb = *reinterpret_cast<const ulonglong2*>(row + 4);
        fma2(acc[0][0], xa.x, w0); fma2(acc[0][1], xa.x, w1); fma2(acc[0][2], xa.x, w2); fma2(acc[0][3], xa.x, w3);
        fma2(acc[1][0], xa.y, w0); fma2(acc[1][1], xa.y, w1); fma2(acc[1][2], xa.y, w2); fma2(acc[1][3], xa.y, w3);
        fma2(acc[2][0], xb.x, w0); fma2(acc[2][1], xb.x, w1); fma2(acc[2][2], xb.x, w2); fma2(acc[2][3], xb.x, w3);
        fma2(acc[3][0], xb.y, w0); fma2(acc[3][1], xb.y, w1); fma2(acc[3][2], xb.y, w2); fma2(acc[3][3], xb.y, w3);
    }
}
__device__ __forceinline__ void gemmB(ull (&acc)[2][4], const float* __restrict__ W, int ld, int K,
                                      const float* sInT, int c0, int r0) {
#pragma unroll 4
    for (int k = 0; k < K; k++) {
        float4 w = __ldg(reinterpret_cast<const float4*>(W + (size_t)k * ld + c0));
        ull w0 = pk2(w.x, w.x), w1 = pk2(w.y, w.y), w2 = pk2(w.z, w.z), w3 = pk2(w.w, w.w);
        ulonglong2 xa = *reinterpret_cast<const ulonglong2*>(sInT + k * SROW + r0);
        fma2(acc[0][0], xa.x, w0); fma2(acc[0][1], xa.x, w1); fma2(acc[0][2], xa.x, w2); fma2(acc[0][3], xa.x, w3);
        fma2(acc[1][0], xa.y, w0); fma2(acc[1][1], xa.y, w1); fma2(acc[1][2], xa.y, w2); fma2(acc[1][3], xa.y, w3);
    }
}
template <int NP>
__device__ __forceinline__ void init_bias(ull (&acc)[NP][4], const float* __restrict__ b, int c0) {
#pragma unroll
    for (int c = 0; c < 4; c++) {
        float bv = b[c0 + c]; ull bb = pk2(bv, bv);
#pragma unroll
        for (int p = 0; p < NP; p++) acc[p][c] = bb;
    }
}
__device__ __forceinline__ void relu_store_hT(ull (&acc)[4][4], float* sHT, int c0, int r0) {
#pragma unroll
    for (int p = 0; p < 4; p++)
#pragma unroll
        for (int c = 0; c < 4; c++) {
            float a, b; upk2(acc[p][c], a, b);
            *reinterpret_cast<float2*>(&sHT[(c0 + c) * SROW + r0 + 2 * p]) =
                make_float2(fmaxf(a, 0.f), fmaxf(b, 0.f));
        }
}

__global__ void __launch_bounds__(128)
k_encode_node(const float* __restrict__ nf, const float* __restrict__ emb,
              const float* __restrict__ W0, const float* __restrict__ b0,
              const float* __restrict__ W1, const float* __restrict__ b1, int N) {
    __shared__ float sInT[47 * SROW];
    __shared__ float sHT[128 * SROW];
    __shared__ int sPT[32];
    int t = threadIdx.x, base = blockIdx.x * 32;
    if (t < 32) { int n = min(base + t, N - 1); sPT[t] = (int)(nf[n * 32 + 31] + 0.5f); }
    __syncthreads();
    for (int i = t; i < 32 * 47; i += 128) {
        int r = i / 47, k = i - r * 47;
        int n = min(base + r, N - 1);
        sInT[k * SROW + r] = (k < 31) ? nf[n * 32 + k] : emb[sPT[r] * 16 + (k - 31)];
    }
    __syncthreads();
    int w = t >> 5, l = t & 31;
    int c0 = 32 * w + (l & 7) * 4, r0 = (l >> 3) * 8;
    ull acc[4][4];
    init_bias<4>(acc, b0, c0);
    gemmA(acc, W0, 128, 47, sInT, c0, r0);
    relu_store_hT(acc, sHT, c0, r0);
    __syncthreads();
    ull acc2[4][4];
    init_bias<4>(acc2, b1, c0);
    gemmA(acc2, W1, 128, 128, sHT, c0, r0);
#pragma unroll
    for (int p = 0; p < 4; p++)
#pragma unroll
        for (int c = 0; c < 4; c++) {
            float a, b; upk2(acc2[p][c], a, b);
            int rA = base + r0 + 2 * p;
            if (rA < N)     g_node[(size_t)rA * 128 + c0 + c] = a;
            if (rA + 1 < N) g_node[(size_t)(rA + 1) * 128 + c0 + c] = b;
        }
}

__global__ void __launch_bounds__(128)
k_node_core(const float* __restrict__ W0, const float* __restrict__ b0,
            const float* __restrict__ W1, const float* __restrict__ b1, int N) {
    __shared__ float sInT[128 * SROW];
    __shared__ float sHT[128 * SROW];
    __shared__ float sInv[32];
    int t = threadIdx.x, base = blockIdx.x * 32;
    if (t < 32) { int n = min(base + t, N - 1); sInv[t] = 1.0f / fmaxf(g_counts[n], 1.0f); }
    __syncthreads();
    for (int i = t; i < 32 * 128; i += 128) {
        int r = i >> 7, k = i & 127;
        int n = min(base + r, N - 1);
        sInT[k * SROW + r] = (k < 64) ? g_agg[(size_t)n * 64 + k] * sInv[r]
                                      : g_node[(size_t)n * 128 + 64 + (k - 64)];
    }
    __syncthreads();
    int w = t >> 5, l = t & 31;
    int c0 = 32 * w + (l & 7) * 4, r0 = (l >> 3) * 8;
    ull acc[4][4];
    init_bias<4>(acc, b0, c0);
    gemmA(acc, W0, 128, 128, sInT, c0, r0);
    relu_store_hT(acc, sHT, c0, r0);
    __syncthreads();
    int c0b = 16 * w + (l & 3) * 4, r0b = (l >> 2) * 4;
    ull acc2[2][4];
    init_bias<2>(acc2, b1, c0b);
    gemmB(acc2, W1, 64, 128, sHT, c0b, r0b);
#pragma unroll
    for (int p = 0; p < 2; p++) {
        int rA = r0b + 2 * p, nA = base + rA;
#pragma unroll
        for (int c = 0; c < 4; c++) {
            int col = c0b + c;
            ull oldp = *reinterpret_cast<const ull*>(&sInT[(64 + col) * SROW + rA]);
            ull np = add2(oldp, acc2[p][c]);
            float a, b; upk2(np, a, b);
            if (nA < N)     g_node[(size_t)nA * 128 + 64 + col] = a;
            if (nA + 1 < N) g_node[(size_t)(nA + 1) * 128 + 64 + col] = b;
        }
    }
}

__global__ void __launch_bounds__(128)
k_decode(const float* __restrict__ W0, const float* __restrict__ b0,
         const float* __restrict__ W1, const float* __restrict__ b1,
         float* __restrict__ out, int N) {
    __shared__ float sInT[128 * SROW];
    __shared__ float sHT[128 * SROW];
    int t = threadIdx.x, base = blockIdx.x * 32;
    for (int i = t; i < 32 * 128; i += 128) {
        int r = i >> 7, k = i & 127;
        int n = min(base + r, N - 1);
        sInT[k * SROW + r] = g_node[(size_t)n * 128 + k];
    }
    __syncthreads();
    int w = t >> 5, l = t & 31;
    int c0 = 32 * w + (l & 7) * 4, r0 = (l >> 3) * 8;
    ull acc[4][4];
    init_bias<4>(acc, b0, c0);
    gemmA(acc, W0, 128, 128, sInT, c0, r0);
    relu_store_hT(acc, sHT, c0, r0);
    __syncthreads();
    if (t < 96) {
        int r = t / 3, c = t - 3 * (t / 3);
        float s = b1[c];
#pragma unroll 8
        for (int j = 0; j < 128; j++) s += sHT[j * SROW + r] * W1[j * 3 + c];
        int n = base + r;
        if (n < N) out[n * 3 + c] = s;
    }
}

// ---------------- launch ----------------
extern "C" void kernel_launch(void* const* d_in, const int* in_sizes, int n_in,
                              void* d_out, int out_size) {
    (void)n_in; (void)out_size;
    const int*   ei   = (const int*)d_in[0];
    const float* nf   = (const float*)d_in[1];
    const float* ef   = (const float*)d_in[2];
    const float* emb  = (const float*)d_in[3];
    const float* enW0 = (const float*)d_in[4],  *enb0 = (const float*)d_in[5];
    const float* enW1 = (const float*)d_in[6],  *enb1 = (const float*)d_in[7];
    const float* eeW0 = (const float*)d_in[8],  *eeb0 = (const float*)d_in[9];
    const float* eeW1 = (const float*)d_in[10], *eeb1 = (const float*)d_in[11];
    const float* ceW0 = (const float*)d_in[12], *ceb0 = (const float*)d_in[13];
    const float* ceW1 = (const float*)d_in[14], *ceb1 = (const float*)d_in[15];
    const float* cnW0 = (const float*)d_in[16], *cnb0 = (const float*)d_in[17];
    const float* cnW1 = (const float*)d_in[18], *cnb1 = (const float*)d_in[19];
    const float* dW0  = (const float*)d_in[20], *db0  = (const float*)d_in[21];
    const float* dW1  = (const float*)d_in[22], *db1  = (const float*)d_in[23];
    float* out = (float*)d_out;

    int N = in_sizes[1] / 32;
    int E = in_sizes[0] / 2;
    int nb = (N + 31) / 32;

    const int SM_CORE = CSM_U32 * 4;                    // 121600 bytes
    const int SM_ENC  = (EA_OFF + 128 * 68) * 4;        // 74752
    cudaFuncSetAttribute(k_edge_core_mma, cudaFuncAttributeMaxDynamicSharedMemorySize, SM_CORE);
    cudaFuncSetAttribute(k_encode_edge_mma, cudaFuncAttributeMaxDynamicSharedMemorySize, SM_ENC);

    int prep_tot = 128 * 96 + 64 * 64 + 128 * 8 + 64 * 128;
    k_prep<<<(prep_tot + 255) / 256, 256>>>(ceW0, ceW1, eeW0, eeW1);
    k_zero_counts<<<(N + 255) / 256, 256>>>(N);
    k_counts<<<(E + 255) / 256, 256>>>(ei, E);
    k_encode_node<<<nb, 128>>>(nf, emb, enW0, enb0, enW1, enb1, N);

    int enc_b = (E + 128 * T_ENC - 1) / (128 * T_ENC);
    k_encode_edge_mma<<<enc_b, 256, SM_ENC>>>(ef, eeb0, eeb1 + 64, E);

    int core_b = (E + 128 * T_CORE - 1) / (128 * T_CORE);
    for (int s = 0; s < 3; s++) {
        k_zero_agg<<<(N * 64 + 255) / 256, 256>>>(N * 64);
        k_edge_core_mma<<<core_b, 256, SM_CORE>>>(ei, ceb0, ceb1, E);
        k_node_core<<<nb, 128>>>(cnW0, cnb0, cnW1, cnb1, N);
    }
    k_decode<<<nb, 128>>>(dW0, db0, dW1, db1, out, N);
}

// round 15
// speedup vs baseline: 1.6740x; 1.0895x over previous
#include <cuda_runtime.h>
#include <cuda_bf16.h>
#include <cstdint>

#define SROW 36
#define MAXN 50048
#define MAXE 800032
typedef unsigned long long ull;

__device__ float g_node[(size_t)MAXN * 128];
__device__ float g_edge_tail[(size_t)MAXE * 64];
__device__ float g_agg[(size_t)MAXN * 64];
__device__ float g_counts[MAXN];
__device__ uint32_t g_W0Tb[128 * 96];   // core_e_W0^T bf16x2 [n=128][kpair=96]
__device__ uint32_t g_W1Tb[64 * 64];    // core_e_W1^T bf16x2 [n=64][kpair=64]
__device__ uint32_t g_nW0Tb[128 * 64];  // core_n_W0^T bf16x2 [n=128][kpair=64]
__device__ uint32_t g_nW1Tb[64 * 64];   // core_n_W1^T bf16x2 [n=64][kpair=64]
__device__ float g_eW0T[128 * 8];       // enc_e_W0^T tf32 [n=128][k=8 pad]
__device__ float g_eW1T[64 * 128];      // enc_e_W1[:,64:]^T tf32

// ---------------- helpers ----------------
__device__ __forceinline__ uint32_t f2tf(float x) {
    uint32_t u; asm("cvt.rna.tf32.f32 %0, %1;" : "=r"(u) : "f"(x));
    return u;
}
__device__ __forceinline__ uint32_t pkbf(float lo, float hi) {
    uint32_t r; asm("cvt.rn.bf16x2.f32 %0, %1, %2;" : "=r"(r) : "f"(hi), "f"(lo));
    return r;
}
#define MMA8(d, a0, a1, a2, a3, b0, b1)                                        \
    asm volatile(                                                              \
        "mma.sync.aligned.m16n8k8.row.col.f32.tf32.tf32.f32 "                  \
        "{%0,%1,%2,%3}, {%4,%5,%6,%7}, {%8,%9}, {%0,%1,%2,%3};"                \
        : "+f"((d)[0]), "+f"((d)[1]), "+f"((d)[2]), "+f"((d)[3])               \
        : "r"(a0), "r"(a1), "r"(a2), "r"(a3), "r"(b0), "r"(b1))
#define MMA16(d, a0, a1, a2, a3, b0, b1)                                       \
    asm volatile(                                                              \
        "mma.sync.aligned.m16n8k16.row.col.f32.bf16.bf16.f32 "                 \
        "{%0,%1,%2,%3}, {%4,%5,%6,%7}, {%8,%9}, {%0,%1,%2,%3};"                \
        : "+f"((d)[0]), "+f"((d)[1]), "+f"((d)[2]), "+f"((d)[3])               \
        : "r"(a0), "r"(a1), "r"(a2), "r"(a3), "r"(b0), "r"(b1))
#define REDV2(p, x0, x1)                                                       \
    asm volatile("red.global.add.v2.f32 [%0], {%1,%2};"                        \
        :: "l"(p), "f"(x0), "f"(x1) : "memory")
#define BAR128(id) asm volatile("bar.sync %0, %1;" :: "r"(id), "r"(128) : "memory")

// ---------------- small kernels ----------------
__global__ void k_prep(const float* __restrict__ ceW0, const float* __restrict__ ceW1,
                       const float* __restrict__ eeW0, const float* __restrict__ eeW1,
                       const float* __restrict__ cnW0, const float* __restrict__ cnW1) {
    int i = blockIdx.x * 256 + threadIdx.x;
    if (i < 128 * 96) {
        int n = i / 96, j = i % 96;
        g_W0Tb[i] = pkbf(ceW0[(2 * j) * 128 + n], ceW0[(2 * j + 1) * 128 + n]);
    }
    int j2 = i - 128 * 96;
    if (j2 >= 0 && j2 < 64 * 64) {
        int n = j2 / 64, j = j2 % 64;
        g_W1Tb[j2] = pkbf(ceW1[(2 * j) * 64 + n], ceW1[(2 * j + 1) * 64 + n]);
    }
    int m = j2 - 64 * 64;
    if (m >= 0 && m < 128 * 8) { int n = m / 8, k = m % 8; g_eW0T[m] = (k < 3) ? __uint_as_float(f2tf(eeW0[k * 128 + n])) : 0.f; }
    int q = m - 128 * 8;
    if (q >= 0 && q < 64 * 128) { int n = q / 128, k = q % 128; g_eW1T[q] = __uint_as_float(f2tf(eeW1[k * 128 + 64 + n])); }
    int r = q - 64 * 128;
    if (r >= 0 && r < 128 * 64) {
        int n = r / 64, j = r % 64;
        g_nW0Tb[r] = pkbf(cnW0[(2 * j) * 128 + n], cnW0[(2 * j + 1) * 128 + n]);
    }
    int s = r - 128 * 64;
    if (s >= 0 && s < 64 * 64) {
        int n = s / 64, j = s % 64;
        g_nW1Tb[s] = pkbf(cnW1[(2 * j) * 64 + n], cnW1[(2 * j + 1) * 64 + n]);
    }
}
__global__ void k_zero_counts(int n) { int i = blockIdx.x*256+threadIdx.x; if (i < n) g_counts[i] = 0.f; }
__global__ void k_zero_agg(int n)    { int i = blockIdx.x*256+threadIdx.x; if (i < n) g_agg[i] = 0.f; }
__global__ void k_counts(const int* __restrict__ ei, int E) {
    int e = blockIdx.x*256+threadIdx.x;
    if (e < E) atomicAdd(&g_counts[ei[E + e]], 1.0f);
}

// ---------------------------------------------------------------------------
// core edge step, bf16 mma.m16n8k16, 256 threads = 2(m) x 4(n) warp grid
// ---------------------------------------------------------------------------
#define T_CORE 4
#define CW1_OFF 12800
#define CA_OFF  17152
#define CIDX_OFF 29952
#define CB0_OFF 30208
#define CB1_OFF 30336
#define CSM_U32 30400
__global__ void __launch_bounds__(256, 1)
k_edge_core_mma(const int* __restrict__ ei, const float* __restrict__ b0g,
                const float* __restrict__ b1g, int E) {
    extern __shared__ uint32_t smu[];
    uint32_t* sW0 = smu;
    uint32_t* sW1 = smu + CW1_OFF;
    uint32_t* sA  = smu + CA_OFF;
    int*   sIdx = (int*)(smu + CIDX_OFF);
    float* sB0 = (float*)(smu + CB0_OFF);
    float* sB1 = (float*)(smu + CB1_OFF);
    int t = threadIdx.x, w = t >> 5, lane = t & 31;
    int tg = lane & 3, lg = lane >> 2;
    int wm = w >> 2, wn = w & 3;
    int RB = wm * 64, NB = wn * 32, NB2 = wn * 16;
    int rsub = lane >> 3, seg = lane & 7;
    int GR = 16 * w;

    for (int i = t; i < 128 * 24; i += 256) {
        int n = i / 24, j = i % 24;
        *(uint4*)(sW0 + n * 100 + j * 4) = *(const uint4*)(g_W0Tb + n * 96 + j * 4);
    }
    for (int i = t; i < 64 * 16; i += 256) {
        int n = i / 16, j = i % 16;
        *(uint4*)(sW1 + n * 68 + j * 4) = *(const uint4*)(g_W1Tb + n * 64 + j * 4);
    }
    if (t < 128) sB0[t] = b0g[t];
    else if (t < 192) sB1[t - 128] = b1g[t - 128];
    __syncthreads();

    for (int tt = 0; tt < T_CORE; tt++) {
        int base = (blockIdx.x * T_CORE + tt) * 128;
        if (base >= E) break;
        __syncthreads();
        if (t < 128) {
            int e = min(base + t, E - 1);
            sIdx[t] = ei[E + e];
            sIdx[128 + t] = ei[e];
        }
        __syncthreads();

#pragma unroll
        for (int it = 0; it < 4; it++) {
            int row = GR + it * 4 + rsub;
            int er = min(base + row, E - 1);
            const float* p0 = g_edge_tail + (size_t)er * 64;
            const float* p1 = g_node + (size_t)sIdx[row] * 128 + 64;
            const float* p2 = g_node + (size_t)sIdx[128 + row] * 128 + 64;
#pragma unroll
            for (int ch = 0; ch < 3; ch++) {
                const float* p = (ch == 0) ? p0 : (ch == 1) ? p1 : p2;
                float4 v0 = *(const float4*)(p + seg * 8);
                float4 v1 = *(const float4*)(p + seg * 8 + 4);
                uint4 u;
                u.x = pkbf(v0.x, v0.y); u.y = pkbf(v0.z, v0.w);
                u.z = pkbf(v1.x, v1.y); u.w = pkbf(v1.z, v1.w);
                *(uint4*)(sA + row * 100 + ch * 32 + seg * 4) = u;
            }
        }
        BAR128(1 + wm);

        float d1[4][4][4];
#pragma unroll
        for (int m = 0; m < 4; m++)
#pragma unroll
            for (int n0 = 0; n0 < 4; n0++)
#pragma unroll
                for (int c = 0; c < 4; c++) d1[m][n0][c] = 0.f;

        for (int ks = 0; ks < 12; ks++) {
            uint32_t bf0[4], bf1[4];
#pragma unroll
            for (int n0 = 0; n0 < 4; n0++) {
                const uint32_t* bp = sW0 + (NB + n0 * 8 + lg) * 100 + ks * 8 + tg;
                bf0[n0] = bp[0]; bf1[n0] = bp[4];
            }
#pragma unroll
            for (int m = 0; m < 4; m++) {
                const uint32_t* ap = sA + (RB + m * 16 + lg) * 100 + ks * 8 + tg;
                uint32_t a0 = ap[0], a2 = ap[4], a1 = ap[800], a3 = ap[804];
#pragma unroll
                for (int n0 = 0; n0 < 4; n0++)
                    MMA16(d1[m][n0], a0, a1, a2, a3, bf0[n0], bf1[n0]);
            }
        }
        BAR128(1 + wm);

#pragma unroll
        for (int m = 0; m < 4; m++)
#pragma unroll
            for (int n0 = 0; n0 < 4; n0++) {
                int cb = NB + n0 * 8 + 2 * tg;
                float ba = sB0[cb], bb = sB0[cb + 1];
                float h0 = fmaxf(d1[m][n0][0] + ba, 0.f), h1 = fmaxf(d1[m][n0][1] + bb, 0.f);
                float h2 = fmaxf(d1[m][n0][2] + ba, 0.f), h3 = fmaxf(d1[m][n0][3] + bb, 0.f);
                int r = RB + m * 16 + lg;
                sA[r * 100 + (cb >> 1)] = pkbf(h0, h1);
                sA[(r + 8) * 100 + (cb >> 1)] = pkbf(h2, h3);
            }
        BAR128(1 + wm);

        float d2[4][2][4];
#pragma unroll
        for (int m = 0; m < 4; m++)
#pragma unroll
            for (int n0 = 0; n0 < 2; n0++)
#pragma unroll
                for (int c = 0; c < 4; c++) d2[m][n0][c] = 0.f;

        for (int ks = 0; ks < 8; ks++) {
            uint32_t bf0[2], bf1[2];
#pragma unroll
            for (int n0 = 0; n0 < 2; n0++) {
                const uint32_t* bp = sW1 + (NB2 + n0 * 8 + lg) * 68 + ks * 8 + tg;
                bf0[n0] = bp[0]; bf1[n0] = bp[4];
            }
#pragma unroll
            for (int m = 0; m < 4; m++) {
                const uint32_t* ap = sA + (RB + m * 16 + lg) * 100 + ks * 8 + tg;
                uint32_t a0 = ap[0], a2 = ap[4], a1 = ap[800], a3 = ap[804];
#pragma unroll
                for (int n0 = 0; n0 < 2; n0++)
                    MMA16(d2[m][n0], a0, a1, a2, a3, bf0[n0], bf1[n0]);
            }
        }

        // epilogue: tail += d2 + b1 ; store ; red.v2 into agg[dst]
#pragma unroll
        for (int m = 0; m < 4; m++)
#pragma unroll
            for (int n0 = 0; n0 < 2; n0++) {
                int cb = NB2 + n0 * 8 + 2 * tg;
                float ba = sB1[cb], bb = sB1[cb + 1];
                int r0 = RB + m * 16 + lg;
                int e0 = base + r0;
                if (e0 < E) {
                    float2 rv = *(const float2*)(g_edge_tail + (size_t)e0 * 64 + cb);
                    float x0 = d2[m][n0][0] + ba + rv.x, x1 = d2[m][n0][1] + bb + rv.y;
                    *(float2*)(g_edge_tail + (size_t)e0 * 64 + cb) = make_float2(x0, x1);
                    REDV2(g_agg + (size_t)sIdx[r0] * 64 + cb, x0, x1);
                }
                int r1 = r0 + 8, e1 = base + r1;
                if (e1 < E) {
                    float2 rv = *(const float2*)(g_edge_tail + (size_t)e1 * 64 + cb);
                    float x0 = d2[m][n0][2] + ba + rv.x, x1 = d2[m][n0][3] + bb + rv.y;
                    *(float2*)(g_edge_tail + (size_t)e1 * 64 + cb) = make_float2(x0, x1);
                    REDV2(g_agg + (size_t)sIdx[r1] * 64 + cb, x0, x1);
                }
            }
    }
}

// ---------------------------------------------------------------------------
// node core, bf16 mma: ninp=[agg/cnt | node_tail] (K=128) -> 128 relu -> 64, +res
// smem u32: sW0[128][68] | sW1[64][68] | sA[128][68] | b0[128] | b1[64]
// ---------------------------------------------------------------------------
#define T_NODE 2
#define NW1_OFF 8704
#define NA_OFF  13056
#define NB0_OFF 21760
#define NB1_OFF 21888
#define NSM_U32 21952
__global__ void __launch_bounds__(256, 1)
k_node_core_mma(const float* __restrict__ b0g, const float* __restrict__ b1g, int N) {
    extern __shared__ uint32_t smu[];
    uint32_t* sW0 = smu;
    uint32_t* sW1 = smu + NW1_OFF;
    uint32_t* sA  = smu + NA_OFF;
    float* sB0 = (float*)(smu + NB0_OFF);
    float* sB1 = (float*)(smu + NB1_OFF);
    int t = threadIdx.x, w = t >> 5, lane = t & 31;
    int tg = lane & 3, lg = lane >> 2;
    int wm = w >> 2, wn = w & 3;
    int RB = wm * 64, NB = wn * 32, NB2 = wn * 16;
    int rsub = lane >> 3, seg = lane & 7;
    int GR = 16 * w;

    for (int i = t; i < 128 * 16; i += 256) {
        int n = i / 16, j = i % 16;
        *(uint4*)(sW0 + n * 68 + j * 4) = *(const uint4*)(g_nW0Tb + n * 64 + j * 4);
    }
    for (int i = t; i < 64 * 16; i += 256) {
        int n = i / 16, j = i % 16;
        *(uint4*)(sW1 + n * 68 + j * 4) = *(const uint4*)(g_nW1Tb + n * 64 + j * 4);
    }
    if (t < 128) sB0[t] = b0g[t];
    else if (t < 192) sB1[t - 128] = b1g[t - 128];
    __syncthreads();

    for (int tt = 0; tt < T_NODE; tt++) {
        int base = (blockIdx.x * T_NODE + tt) * 128;
        if (base >= N) break;
        if (tt) BAR128(1 + wm);               // band free from prior tile's layer2
#pragma unroll
        for (int it = 0; it < 4; it++) {
            int row = GR + it * 4 + rsub;
            int n = min(base + row, N - 1);
            float inv = 1.0f / fmaxf(g_counts[n], 1.0f);
            const float* p0 = g_agg + (size_t)n * 64;
            const float* p1 = g_node + (size_t)n * 128 + 64;
#pragma unroll
            for (int ch = 0; ch < 2; ch++) {
                const float* p = (ch == 0) ? p0 : p1;
                float4 v0 = *(const float4*)(p + seg * 8);
                float4 v1 = *(const float4*)(p + seg * 8 + 4);
                if (ch == 0) {
                    v0.x *= inv; v0.y *= inv; v0.z *= inv; v0.w *= inv;
                    v1.x *= inv; v1.y *= inv; v1.z *= inv; v1.w *= inv;
                }
                uint4 u;
                u.x = pkbf(v0.x, v0.y); u.y = pkbf(v0.z, v0.w);
                u.z = pkbf(v1.x, v1.y); u.w = pkbf(v1.z, v1.w);
                *(uint4*)(sA + row * 68 + ch * 32 + seg * 4) = u;
            }
        }
        BAR128(1 + wm);

        float d1[4][4][4];
#pragma unroll
        for (int m = 0; m < 4; m++)
#pragma unroll
            for (int n0 = 0; n0 < 4; n0++)
#pragma unroll
                for (int c = 0; c < 4; c++) d1[m][n0][c] = 0.f;

        for (int ks = 0; ks < 8; ks++) {
            uint32_t bf0[4], bf1[4];
#pragma unroll
            for (int n0 = 0; n0 < 4; n0++) {
                const uint32_t* bp = sW0 + (NB + n0 * 8 + lg) * 68 + ks * 8 + tg;
                bf0[n0] = bp[0]; bf1[n0] = bp[4];
            }
#pragma unroll
            for (int m = 0; m < 4; m++) {
                const uint32_t* ap = sA + (RB + m * 16 + lg) * 68 + ks * 8 + tg;
                uint32_t a0 = ap[0], a2 = ap[4], a1 = ap[544], a3 = ap[548];
#pragma unroll
                for (int n0 = 0; n0 < 4; n0++)
                    MMA16(d1[m][n0], a0, a1, a2, a3, bf0[n0], bf1[n0]);
            }
        }
        BAR128(1 + wm);

#pragma unroll
        for (int m = 0; m < 4; m++)
#pragma unroll
            for (int n0 = 0; n0 < 4; n0++) {
                int cb = NB + n0 * 8 + 2 * tg;
                float ba = sB0[cb], bb = sB0[cb + 1];
                float h0 = fmaxf(d1[m][n0][0] + ba, 0.f), h1 = fmaxf(d1[m][n0][1] + bb, 0.f);
                float h2 = fmaxf(d1[m][n0][2] + ba, 0.f), h3 = fmaxf(d1[m][n0][3] + bb, 0.f);
                int r = RB + m * 16 + lg;
                sA[r * 68 + (cb >> 1)] = pkbf(h0, h1);
                sA[(r + 8) * 68 + (cb >> 1)] = pkbf(h2, h3);
            }
        BAR128(1 + wm);

        float d2[4][2][4];
#pragma unroll
        for (int m = 0; m < 4; m++)
#pragma unroll
            for (int n0 = 0; n0 < 2; n0++)
#pragma unroll
                for (int c = 0; c < 4; c++) d2[m][n0][c] = 0.f;

        for (int ks = 0; ks < 8; ks++) {
            uint32_t bf0[2], bf1[2];
#pragma unroll
            for (int n0 = 0; n0 < 2; n0++) {
                const uint32_t* bp = sW1 + (NB2 + n0 * 8 + lg) * 68 + ks * 8 + tg;
                bf0[n0] = bp[0]; bf1[n0] = bp[4];
            }
#pragma unroll
            for (int m = 0; m < 4; m++) {
                const uint32_t* ap = sA + (RB + m * 16 + lg) * 68 + ks * 8 + tg;
                uint32_t a0 = ap[0], a2 = ap[4], a1 = ap[544], a3 = ap[548];
#pragma unroll
                for (int n0 = 0; n0 < 2; n0++)
                    MMA16(d2[m][n0], a0, a1, a2, a3, bf0[n0], bf1[n0]);
            }
        }

        // epilogue: node_tail += d2 + b1 (residual re-read from g_node)
#pragma unroll
        for (int m = 0; m < 4; m++)
#pragma unroll
            for (int n0 = 0; n0 < 2; n0++) {
                int cb = NB2 + n0 * 8 + 2 * tg;
                float ba = sB1[cb], bb = sB1[cb + 1];
                int r0 = RB + m * 16 + lg;
                int nA = base + r0;
                if (nA < N) {
                    float* pn = g_node + (size_t)nA * 128 + 64 + cb;
                    float2 rv = *(const float2*)pn;
                    *(float2*)pn = make_float2(d2[m][n0][0] + ba + rv.x,
                                               d2[m][n0][1] + bb + rv.y);
                }
                int nB = base + r0 + 8;
                if (nB < N) {
                    float* pn = g_node + (size_t)nB * 128 + 64 + cb;
                    float2 rv = *(const float2*)pn;
                    *(float2*)pn = make_float2(d2[m][n0][2] + ba + rv.x,
                                               d2[m][n0][3] + bb + rv.y);
                }
            }
    }
}

// ---------------------------------------------------------------------------
// encode edge, tensor tf32 (unchanged)
// ---------------------------------------------------------------------------
#define T_ENC 8
#define EW1_OFF 1536
#define EA_OFF  9984
__global__ void __launch_bounds__(256, 1)
k_encode_edge_mma(const float* __restrict__ ef, const float* __restrict__ b0g,
                  const float* __restrict__ b1g, int E) {
    extern __shared__ float sm[];
    float* sW0 = sm;
    float* sW1 = sm + EW1_OFF;
    float* sA  = sm + EA_OFF;
    int t = threadIdx.x, w = t >> 5, lane = t & 31;
    int tg = lane & 3, lg = lane >> 2, rb = 16 * w;

    for (int i = t; i < 128 * 2; i += 256) {
        int n = i / 2, j = i % 2;
        *(float4*)(sW0 + n * 12 + j * 4) = *(const float4*)(g_eW0T + n * 8 + j * 4);
    }
    for (int i = t; i < 64 * 32; i += 256) {
        int n = i / 32, j = i % 32;
        *(float4*)(sW1 + n * 132 + j * 4) = *(const float4*)(g_eW1T + n * 128 + j * 4);
    }
    __syncthreads();

    for (int tt = 0; tt < T_ENC; tt++) {
        int base = (blockIdx.x * T_ENC + tt) * 128;
        if (base >= E) break;
        int row = t >> 1, half = t & 1;
        int er = min(base + row, E - 1);
        {
            float* dst = sA + row * 68 + half * 4;
            if (half == 0) {
                *(float4*)dst = make_float4(
                    __uint_as_float(f2tf(ef[er * 3 + 0])),
                    __uint_as_float(f2tf(ef[er * 3 + 1])),
                    __uint_as_float(f2tf(ef[er * 3 + 2])), 0.f);
            } else {
                *(float4*)dst = make_float4(0.f, 0.f, 0.f, 0.f);
            }
        }
        __syncwarp();

        float d1[16][4];
#pragma unroll
        for (int n0 = 0; n0 < 16; n0++)
#pragma unroll
            for (int c = 0; c < 4; c++) d1[n0][c] = 0.f;
        {
            uint32_t a0 = __float_as_uint(sA[(rb + lg) * 68 + tg]);
            uint32_t a1 = __float_as_uint(sA[(rb + lg + 8) * 68 + tg]);
            uint32_t a2 = __float_as_uint(sA[(rb + lg) * 68 + tg + 4]);
            uint32_t a3 = __float_as_uint(sA[(rb + lg + 8) * 68 + tg + 4]);
#pragma unroll
            for (int n0 = 0; n0 < 16; n0++) {
                uint32_t b0 = __float_as_uint(sW0[(n0 * 8 + lg) * 12 + tg]);
                uint32_t b1 = __float_as_uint(sW0[(n0 * 8 + lg) * 12 + tg + 4]);
                MMA8(d1[n0], a0, a1, a2, a3, b0, b1);
            }
        }
        __syncwarp();

        float d2[8][4];
#pragma unroll
        for (int n0 = 0; n0 < 8; n0++)
#pragma unroll
            for (int c = 0; c < 4; c++) d2[n0][c] = 0.f;

        for (int nh = 0; nh < 2; nh++) {
#pragma unroll
            for (int q = 0; q < 8; q++) {
                int n0 = nh * 8 + q;
                int c0 = n0 * 8 + 2 * tg, cl = c0 - nh * 64;
                float ba = __ldg(b0g + c0), bb = __ldg(b0g + c0 + 1);
                float h0 = fmaxf(d1[n0][0] + ba, 0.f), h1 = fmaxf(d1[n0][1] + bb, 0.f);
                float h2 = fmaxf(d1[n0][2] + ba, 0.f), h3 = fmaxf(d1[n0][3] + bb, 0.f);
                *(float2*)(sA + (rb + lg) * 68 + cl) =
                    make_float2(__uint_as_float(f2tf(h0)), __uint_as_float(f2tf(h1)));
                *(float2*)(sA + (rb + lg + 8) * 68 + cl) =
                    make_float2(__uint_as_float(f2tf(h2)), __uint_as_float(f2tf(h3)));
            }
            __syncwarp();
            for (int k0 = 0; k0 < 8; k0++) {
                int kb = k0 * 8 + tg;
                uint32_t a0 = __float_as_uint(sA[(rb + lg) * 68 + kb]);
                uint32_t a1 = __float_as_uint(sA[(rb + lg + 8) * 68 + kb]);
                uint32_t a2 = __float_as_uint(sA[(rb + lg) * 68 + kb + 4]);
                uint32_t a3 = __float_as_uint(sA[(rb + lg + 8) * 68 + kb + 4]);
                int kg = nh * 64 + k0 * 8 + tg;
#pragma unroll
                for (int n0 = 0; n0 < 8; n0++) {
                    uint32_t b0 = __float_as_uint(sW1[(n0 * 8 + lg) * 132 + kg]);
                    uint32_t b1 = __float_as_uint(sW1[(n0 * 8 + lg) * 132 + kg + 4]);
                    MMA8(d2[n0], a0, a1, a2, a3, b0, b1);
                }
            }
            __syncwarp();
        }

        int r0 = rb + lg, r1 = r0 + 8;
#pragma unroll
        for (int n0 = 0; n0 < 8; n0++) {
            int c = n0 * 8 + 2 * tg;
            float ba = __ldg(b1g + c), bb = __ldg(b1g + c + 1);
            int e0 = base + r0;
            if (e0 < E)
                *(float2*)(g_edge_tail + (size_t)e0 * 64 + c) =
                    make_float2(d2[n0][0] + ba, d2[n0][1] + bb);
            int e1 = base + r1;
            if (e1 < E)
                *(float2*)(g_edge_tail + (size_t)e1 * 64 + c) =
                    make_float2(d2[n0][2] + ba, d2[n0][3] + bb);
        }
        __syncwarp();
    }
}

// ---------------- scalar fp32 encode_node / decode ----------------
__device__ __forceinline__ ull pk2(float a, float b) { ull r; asm("mov.b64 %0, {%1, %2};" : "=l"(r) : "f"(a), "f"(b)); return r; }
__device__ __forceinline__ void upk2(ull v, float &a, float &b) { asm("mov.b64 {%0, %1}, %2;" : "=f"(a), "=f"(b) : "l"(v)); }
__device__ __forceinline__ void fma2(ull &d, ull a, ull b) { asm("fma.rn.f32x2 %0, %1, %2, %3;" : "=l"(d) : "l"(a), "l"(b), "l"(d)); }
__device__ __forceinline__ void gemmA(ull (&acc)[4][4], const float* __restrict__ W, int ld, int K,
                                      const float* sInT, int c0, int r0) {
#pragma unroll 4
    for (int k = 0; k < K; k++) {
        float4 w = __ldg(reinterpret_cast<const float4*>(W + (size_t)k * ld + c0));
        ull w0 = pk2(w.x, w.x), w1 = pk2(w.y, w.y), w2 = pk2(w.z, w.z), w3 = pk2(w.w, w.w);
        const float* row = sInT + k * SROW + r0;
        ulonglong2 xa = *reinterpret_cast<const ulonglong2*>(row);
        ulonglong2 xb = *reinterpret_cast<const ulonglong2*>(row + 4);
        fma2(acc[0][0], xa.x, w0); fma2(acc[0][1], xa.x, w1); fma2(acc[0][2], xa.x, w2); fma2(acc[0][3], xa.x, w3);
        fma2(acc[1][0], xa.y, w0); fma2(acc[1][1], xa.y, w1); fma2(acc[1][2], xa.y, w2); fma2(acc[1][3], xa.y, w3);
        fma2(acc[2][0], xb.x, w0); fma2(acc[2][1], xb.x, w1); fma2(acc[2][2], xb.x, w2); fma2(acc[2][3], xb.x, w3);
        fma2(acc[3][0], xb.y, w0); fma2(acc[3][1], xb.y, w1); fma2(acc[3][2], xb.y, w2); fma2(acc[3][3], xb.y, w3);
    }
}
template <int NP>
__device__ __forceinline__ void init_bias(ull (&acc)[NP][4], const float* __restrict__ b, int c0) {
#pragma unroll
    for (int c = 0; c < 4; c++) {
        float bv = b[c0 + c]; ull bb = pk2(bv, bv);
#pragma unroll
        for (int p = 0; p < NP; p++) acc[p][c] = bb;
    }
}
__device__ __forceinline__ void relu_store_hT(ull (&acc)[4][4], float* sHT, int c0, int r0) {
#pragma unroll
    for (int p = 0; p < 4; p++)
#pragma unroll
        for (int c = 0; c < 4; c++) {
            float a, b; upk2(acc[p][c], a, b);
            *reinterpret_cast<float2*>(&sHT[(c0 + c) * SROW + r0 + 2 * p]) =
                make_float2(fmaxf(a, 0.f), fmaxf(b, 0.f));
        }
}

__global__ void __launch_bounds__(128)
k_encode_node(const float* __restrict__ nf, const float* __restrict__ emb,
              const float* __restrict__ W0, const float* __restrict__ b0,
              const float* __restrict__ W1, const float* __restrict__ b1, int N) {
    __shared__ float sInT[47 * SROW];
    __shared__ float sHT[128 * SROW];
    __shared__ int sPT[32];
    int t = threadIdx.x, base = blockIdx.x * 32;
    if (t < 32) { int n = min(base + t, N - 1); sPT[t] = (int)(nf[n * 32 + 31] + 0.5f); }
    __syncthreads();
    for (int i = t; i < 32 * 47; i += 128) {
        int r = i / 47, k = i - r * 47;
        int n = min(base + r, N - 1);
        sInT[k * SROW + r] = (k < 31) ? nf[n * 32 + k] : emb[sPT[r] * 16 + (k - 31)];
    }
    __syncthreads();
    int w = t >> 5, l = t & 31;
    int c0 = 32 * w + (l & 7) * 4, r0 = (l >> 3) * 8;
    ull acc[4][4];
    init_bias<4>(acc, b0, c0);
    gemmA(acc, W0, 128, 47, sInT, c0, r0);
    relu_store_hT(acc, sHT, c0, r0);
    __syncthreads();
    ull acc2[4][4];
    init_bias<4>(acc2, b1, c0);
    gemmA(acc2, W1, 128, 128, sHT, c0, r0);
#pragma unroll
    for (int p = 0; p < 4; p++)
#pragma unroll
        for (int c = 0; c < 4; c++) {
            float a, b; upk2(acc2[p][c], a, b);
            int rA = base + r0 + 2 * p;
            if (rA < N)     g_node[(size_t)rA * 128 + c0 + c] = a;
            if (rA + 1 < N) g_node[(size_t)(rA + 1) * 128 + c0 + c] = b;
        }
}

__global__ void __launch_bounds__(128)
k_decode(const float* __restrict__ W0, const float* __restrict__ b0,
         const float* __restrict__ W1, const float* __restrict__ b1,
         float* __restrict__ out, int N) {
    __shared__ float sInT[128 * SROW];
    __shared__ float sHT[128 * SROW];
    int t = threadIdx.x, base = blockIdx.x * 32;
    for (int i = t; i < 32 * 128; i += 128) {
        int r = i >> 7, k = i & 127;
        int n = min(base + r, N - 1);
        sInT[k * SROW + r] = g_node[(size_t)n * 128 + k];
    }
    __syncthreads();
    int w = t >> 5, l = t & 31;
    int c0 = 32 * w + (l & 7) * 4, r0 = (l >> 3) * 8;
    ull acc[4][4];
    init_bias<4>(acc, b0, c0);
    gemmA(acc, W0, 128, 128, sInT, c0, r0);
    relu_store_hT(acc, sHT, c0, r0);
    __syncthreads();
    if (t < 96) {
        int r = t / 3, c = t - 3 * (t / 3);
        float s = b1[c];
#pragma unroll 8
        for (int j = 0; j < 128; j++) s += sHT[j * SROW + r] * W1[j * 3 + c];
        int n = base + r;
        if (n < N) out[n * 3 + c] = s;
    }
}

// ---------------- launch ----------------
extern "C" void kernel_launch(void* const* d_in, const int* in_sizes, int n_in,
                              void* d_out, int out_size) {
    (void)n_in; (void)out_size;
    const int*   ei   = (const int*)d_in[0];
    const float* nf   = (const float*)d_in[1];
    const float* ef   = (const float*)d_in[2];
    const float* emb  = (const float*)d_in[3];
    const float* enW0 = (const float*)d_in[4],  *enb0 = (const float*)d_in[5];
    const float* enW1 = (const float*)d_in[6],  *enb1 = (const float*)d_in[7];
    const float* eeW0 = (const float*)d_in[8],  *eeb0 = (const float*)d_in[9];
    const float* eeW1 = (const float*)d_in[10], *eeb1 = (const float*)d_in[11];
    const float* ceW0 = (const float*)d_in[12], *ceb0 = (const float*)d_in[13];
    const float* ceW1 = (const float*)d_in[14], *ceb1 = (const float*)d_in[15];
    const float* cnW0 = (const float*)d_in[16], *cnb0 = (const float*)d_in[17];
    const float* cnW1 = (const float*)d_in[18], *cnb1 = (const float*)d_in[19];
    const float* dW0  = (const float*)d_in[20], *db0  = (const float*)d_in[21];
    const float* dW1  = (const float*)d_in[22], *db1  = (const float*)d_in[23];
    float* out = (float*)d_out;

    int N = in_sizes[1] / 32;
    int E = in_sizes[0] / 2;
    int nb = (N + 31) / 32;

    const int SM_CORE = CSM_U32 * 4;                    // 121600
    const int SM_ENC  = (EA_OFF + 128 * 68) * 4;        // 74752
    const int SM_NODE = NSM_U32 * 4;                    // 87808
    cudaFuncSetAttribute(k_edge_core_mma, cudaFuncAttributeMaxDynamicSharedMemorySize, SM_CORE);
    cudaFuncSetAttribute(k_encode_edge_mma, cudaFuncAttributeMaxDynamicSharedMemorySize, SM_ENC);
    cudaFuncSetAttribute(k_node_core_mma, cudaFuncAttributeMaxDynamicSharedMemorySize, SM_NODE);

    int prep_tot = 128 * 96 + 64 * 64 + 128 * 8 + 64 * 128 + 128 * 64 + 64 * 64;
    k_prep<<<(prep_tot + 255) / 256, 256>>>(ceW0, ceW1, eeW0, eeW1, cnW0, cnW1);
    k_zero_counts<<<(N + 255) / 256, 256>>>(N);
    k_counts<<<(E + 255) / 256, 256>>>(ei, E);
    k_encode_node<<<nb, 128>>>(nf, emb, enW0, enb0, enW1, enb1, N);

    int enc_b = (E + 128 * T_ENC - 1) / (128 * T_ENC);
    k_encode_edge_mma<<<enc_b, 256, SM_ENC>>>(ef, eeb0, eeb1 + 64, E);

    int core_b = (E + 128 * T_CORE - 1) / (128 * T_CORE);
    int node_b = (N + 128 * T_NODE - 1) / (128 * T_NODE);
    for (int s = 0; s < 3; s++) {
        k_zero_agg<<<(N * 64 + 255) / 256, 256>>>(N * 64);
        k_edge_core_mma<<<core_b, 256, SM_CORE>>>(ei, ceb0, ceb1, E);
        k_node_core_mma<<<node_b, 256, SM_NODE>>>(cnb0, cnb1, N);
    }
    k_decode<<<nb, 128>>>(dW0, db0, dW1, db1, out, N);
}

// round 16
// speedup vs baseline: 1.7013x; 1.0163x over previous
#include <cuda_runtime.h>
#include <cuda_bf16.h>
#include <cstdint>

#define SROW 36
#define MAXN 50048
#define MAXE 800032
typedef unsigned long long ull;

__device__ float g_node[(size_t)MAXN * 128];
__device__ float g_edge_tail[(size_t)MAXE * 64];
__device__ float g_agg[(size_t)MAXN * 64];
__device__ float g_counts[MAXN];
__device__ uint32_t g_W0Tb[128 * 96];   // core_e_W0^T bf16x2 [n=128][kpair=96]
__device__ uint32_t g_W1Tb[64 * 64];    // core_e_W1^T bf16x2 [n=64][kpair=64]
__device__ uint32_t g_nW0Tb[128 * 64];  // core_n_W0^T bf16x2 [n=128][kpair=64]
__device__ uint32_t g_nW1Tb[64 * 64];   // core_n_W1^T bf16x2 [n=64][kpair=64]
__device__ float g_eW0T[128 * 8];       // enc_e_W0^T tf32 [n=128][k=8 pad]
__device__ uint32_t g_eW1Tb[64 * 64];   // enc_e_W1[:,64:]^T bf16x2 [n=64][kpair=64]

// ---------------- helpers ----------------
__device__ __forceinline__ uint32_t f2tf(float x) {
    uint32_t u; asm("cvt.rna.tf32.f32 %0, %1;" : "=r"(u) : "f"(x));
    return u;
}
__device__ __forceinline__ uint32_t pkbf(float lo, float hi) {
    uint32_t r; asm("cvt.rn.bf16x2.f32 %0, %1, %2;" : "=r"(r) : "f"(hi), "f"(lo));
    return r;
}
#define MMA8(d, a0, a1, a2, a3, b0, b1)                                        \
    asm volatile(                                                              \
        "mma.sync.aligned.m16n8k8.row.col.f32.tf32.tf32.f32 "                  \
        "{%0,%1,%2,%3}, {%4,%5,%6,%7}, {%8,%9}, {%0,%1,%2,%3};"                \
        : "+f"((d)[0]), "+f"((d)[1]), "+f"((d)[2]), "+f"((d)[3])               \
        : "r"(a0), "r"(a1), "r"(a2), "r"(a3), "r"(b0), "r"(b1))
#define MMA16(d, a0, a1, a2, a3, b0, b1)                                       \
    asm volatile(                                                              \
        "mma.sync.aligned.m16n8k16.row.col.f32.bf16.bf16.f32 "                 \
        "{%0,%1,%2,%3}, {%4,%5,%6,%7}, {%8,%9}, {%0,%1,%2,%3};"                \
        : "+f"((d)[0]), "+f"((d)[1]), "+f"((d)[2]), "+f"((d)[3])               \
        : "r"(a0), "r"(a1), "r"(a2), "r"(a3), "r"(b0), "r"(b1))
#define REDV2(p, x0, x1)                                                       \
    asm volatile("red.global.add.v2.f32 [%0], {%1,%2};"                        \
        :: "l"(p), "f"(x0), "f"(x1) : "memory")
#define BAR128(id) asm volatile("bar.sync %0, %1;" :: "r"(id), "r"(128) : "memory")

// ---------------- small kernels ----------------
__global__ void k_prep(const float* __restrict__ ceW0, const float* __restrict__ ceW1,
                       const float* __restrict__ eeW0, const float* __restrict__ eeW1,
                       const float* __restrict__ cnW0, const float* __restrict__ cnW1) {
    int i = blockIdx.x * 256 + threadIdx.x;
    if (i < 128 * 96) {
        int n = i / 96, j = i % 96;
        g_W0Tb[i] = pkbf(ceW0[(2 * j) * 128 + n], ceW0[(2 * j + 1) * 128 + n]);
    }
    int j2 = i - 128 * 96;
    if (j2 >= 0 && j2 < 64 * 64) {
        int n = j2 / 64, j = j2 % 64;
        g_W1Tb[j2] = pkbf(ceW1[(2 * j) * 64 + n], ceW1[(2 * j + 1) * 64 + n]);
    }
    int m = j2 - 64 * 64;
    if (m >= 0 && m < 128 * 8) { int n = m / 8, k = m % 8; g_eW0T[m] = (k < 3) ? __uint_as_float(f2tf(eeW0[k * 128 + n])) : 0.f; }
    int q = m - 128 * 8;
    if (q >= 0 && q < 64 * 64) {
        int n = q / 64, j = q % 64;
        g_eW1Tb[q] = pkbf(eeW1[(2 * j) * 128 + 64 + n], eeW1[(2 * j + 1) * 128 + 64 + n]);
    }
    int r = q - 64 * 64;
    if (r >= 0 && r < 128 * 64) {
        int n = r / 64, j = r % 64;
        g_nW0Tb[r] = pkbf(cnW0[(2 * j) * 128 + n], cnW0[(2 * j + 1) * 128 + n]);
    }
    int s = r - 128 * 64;
    if (s >= 0 && s < 64 * 64) {
        int n = s / 64, j = s % 64;
        g_nW1Tb[s] = pkbf(cnW1[(2 * j) * 64 + n], cnW1[(2 * j + 1) * 64 + n]);
    }
}
__global__ void k_zero_counts(int n) { int i = blockIdx.x*256+threadIdx.x; if (i < n) g_counts[i] = 0.f; }
__global__ void k_zero_agg(int n)    { int i = blockIdx.x*256+threadIdx.x; if (i < n) g_agg[i] = 0.f; }
__global__ void k_counts(const int* __restrict__ ei, int E) {
    int e = blockIdx.x*256+threadIdx.x;
    if (e < E) atomicAdd(&g_counts[ei[E + e]], 1.0f);
}

// ---------------------------------------------------------------------------
// core edge step, bf16 mma.m16n8k16, 256 threads = 2(m) x 4(n) warp grid
// (unchanged from R15 WIN)
// ---------------------------------------------------------------------------
#define T_CORE 4
#define CW1_OFF 12800
#define CA_OFF  17152
#define CIDX_OFF 29952
#define CB0_OFF 30208
#define CB1_OFF 30336
#define CSM_U32 30400
__global__ void __launch_bounds__(256, 1)
k_edge_core_mma(const int* __restrict__ ei, const float* __restrict__ b0g,
                const float* __restrict__ b1g, int E) {
    extern __shared__ uint32_t smu[];
    uint32_t* sW0 = smu;
    uint32_t* sW1 = smu + CW1_OFF;
    uint32_t* sA  = smu + CA_OFF;
    int*   sIdx = (int*)(smu + CIDX_OFF);
    float* sB0 = (float*)(smu + CB0_OFF);
    float* sB1 = (float*)(smu + CB1_OFF);
    int t = threadIdx.x, w = t >> 5, lane = t & 31;
    int tg = lane & 3, lg = lane >> 2;
    int wm = w >> 2, wn = w & 3;
    int RB = wm * 64, NB = wn * 32, NB2 = wn * 16;
    int rsub = lane >> 3, seg = lane & 7;
    int GR = 16 * w;

    for (int i = t; i < 128 * 24; i += 256) {
        int n = i / 24, j = i % 24;
        *(uint4*)(sW0 + n * 100 + j * 4) = *(const uint4*)(g_W0Tb + n * 96 + j * 4);
    }
    for (int i = t; i < 64 * 16; i += 256) {
        int n = i / 16, j = i % 16;
        *(uint4*)(sW1 + n * 68 + j * 4) = *(const uint4*)(g_W1Tb + n * 64 + j * 4);
    }
    if (t < 128) sB0[t] = b0g[t];
    else if (t < 192) sB1[t - 128] = b1g[t - 128];
    __syncthreads();

    for (int tt = 0; tt < T_CORE; tt++) {
        int base = (blockIdx.x * T_CORE + tt) * 128;
        if (base >= E) break;
        __syncthreads();
        if (t < 128) {
            int e = min(base + t, E - 1);
            sIdx[t] = ei[E + e];
            sIdx[128 + t] = ei[e];
        }
        __syncthreads();

#pragma unroll
        for (int it = 0; it < 4; it++) {
            int row = GR + it * 4 + rsub;
            int er = min(base + row, E - 1);
            const float* p0 = g_edge_tail + (size_t)er * 64;
            const float* p1 = g_node + (size_t)sIdx[row] * 128 + 64;
            const float* p2 = g_node + (size_t)sIdx[128 + row] * 128 + 64;
#pragma unroll
            for (int ch = 0; ch < 3; ch++) {
                const float* p = (ch == 0) ? p0 : (ch == 1) ? p1 : p2;
                float4 v0 = *(const float4*)(p + seg * 8);
                float4 v1 = *(const float4*)(p + seg * 8 + 4);
                uint4 u;
                u.x = pkbf(v0.x, v0.y); u.y = pkbf(v0.z, v0.w);
                u.z = pkbf(v1.x, v1.y); u.w = pkbf(v1.z, v1.w);
                *(uint4*)(sA + row * 100 + ch * 32 + seg * 4) = u;
            }
        }
        BAR128(1 + wm);

        float d1[4][4][4];
#pragma unroll
        for (int m = 0; m < 4; m++)
#pragma unroll
            for (int n0 = 0; n0 < 4; n0++)
#pragma unroll
                for (int c = 0; c < 4; c++) d1[m][n0][c] = 0.f;

        for (int ks = 0; ks < 12; ks++) {
            uint32_t bf0[4], bf1[4];
#pragma unroll
            for (int n0 = 0; n0 < 4; n0++) {
                const uint32_t* bp = sW0 + (NB + n0 * 8 + lg) * 100 + ks * 8 + tg;
                bf0[n0] = bp[0]; bf1[n0] = bp[4];
            }
#pragma unroll
            for (int m = 0; m < 4; m++) {
                const uint32_t* ap = sA + (RB + m * 16 + lg) * 100 + ks * 8 + tg;
                uint32_t a0 = ap[0], a2 = ap[4], a1 = ap[800], a3 = ap[804];
#pragma unroll
                for (int n0 = 0; n0 < 4; n0++)
                    MMA16(d1[m][n0], a0, a1, a2, a3, bf0[n0], bf1[n0]);
            }
        }
        BAR128(1 + wm);

#pragma unroll
        for (int m = 0; m < 4; m++)
#pragma unroll
            for (int n0 = 0; n0 < 4; n0++) {
                int cb = NB + n0 * 8 + 2 * tg;
                float ba = sB0[cb], bb = sB0[cb + 1];
                float h0 = fmaxf(d1[m][n0][0] + ba, 0.f), h1 = fmaxf(d1[m][n0][1] + bb, 0.f);
                float h2 = fmaxf(d1[m][n0][2] + ba, 0.f), h3 = fmaxf(d1[m][n0][3] + bb, 0.f);
                int r = RB + m * 16 + lg;
                sA[r * 100 + (cb >> 1)] = pkbf(h0, h1);
                sA[(r + 8) * 100 + (cb >> 1)] = pkbf(h2, h3);
            }
        BAR128(1 + wm);

        float d2[4][2][4];
#pragma unroll
        for (int m = 0; m < 4; m++)
#pragma unroll
            for (int n0 = 0; n0 < 2; n0++)
#pragma unroll
                for (int c = 0; c < 4; c++) d2[m][n0][c] = 0.f;

        for (int ks = 0; ks < 8; ks++) {
            uint32_t bf0[2], bf1[2];
#pragma unroll
            for (int n0 = 0; n0 < 2; n0++) {
                const uint32_t* bp = sW1 + (NB2 + n0 * 8 + lg) * 68 + ks * 8 + tg;
                bf0[n0] = bp[0]; bf1[n0] = bp[4];
            }
#pragma unroll
            for (int m = 0; m < 4; m++) {
                const uint32_t* ap = sA + (RB + m * 16 + lg) * 100 + ks * 8 + tg;
                uint32_t a0 = ap[0], a2 = ap[4], a1 = ap[800], a3 = ap[804];
#pragma unroll
                for (int n0 = 0; n0 < 2; n0++)
                    MMA16(d2[m][n0], a0, a1, a2, a3, bf0[n0], bf1[n0]);
            }
        }

#pragma unroll
        for (int m = 0; m < 4; m++)
#pragma unroll
            for (int n0 = 0; n0 < 2; n0++) {
                int cb = NB2 + n0 * 8 + 2 * tg;
                float ba = sB1[cb], bb = sB1[cb + 1];
                int r0 = RB + m * 16 + lg;
                int e0 = base + r0;
                if (e0 < E) {
                    float2 rv = *(const float2*)(g_edge_tail + (size_t)e0 * 64 + cb);
                    float x0 = d2[m][n0][0] + ba + rv.x, x1 = d2[m][n0][1] + bb + rv.y;
                    *(float2*)(g_edge_tail + (size_t)e0 * 64 + cb) = make_float2(x0, x1);
                    REDV2(g_agg + (size_t)sIdx[r0] * 64 + cb, x0, x1);
                }
                int r1 = r0 + 8, e1 = base + r1;
                if (e1 < E) {
                    float2 rv = *(const float2*)(g_edge_tail + (size_t)e1 * 64 + cb);
                    float x0 = d2[m][n0][2] + ba + rv.x, x1 = d2[m][n0][3] + bb + rv.y;
                    *(float2*)(g_edge_tail + (size_t)e1 * 64 + cb) = make_float2(x0, x1);
                    REDV2(g_agg + (size_t)sIdx[r1] * 64 + cb, x0, x1);
                }
            }
    }
}

// ---------------------------------------------------------------------------
// node core, bf16 mma; gather now ZEROES g_agg after reading (fused zero_agg)
// ---------------------------------------------------------------------------
#define T_NODE 2
#define NW1_OFF 8704
#define NA_OFF  13056
#define NB0_OFF 21760
#define NB1_OFF 21888
#define NSM_U32 21952
__global__ void __launch_bounds__(256, 1)
k_node_core_mma(const float* __restrict__ b0g, const float* __restrict__ b1g, int N) {
    extern __shared__ uint32_t smu[];
    uint32_t* sW0 = smu;
    uint32_t* sW1 = smu + NW1_OFF;
    uint32_t* sA  = smu + NA_OFF;
    float* sB0 = (float*)(smu + NB0_OFF);
    float* sB1 = (float*)(smu + NB1_OFF);
    int t = threadIdx.x, w = t >> 5, lane = t & 31;
    int tg = lane & 3, lg = lane >> 2;
    int wm = w >> 2, wn = w & 3;
    int RB = wm * 64, NB = wn * 32, NB2 = wn * 16;
    int rsub = lane >> 3, seg = lane & 7;
    int GR = 16 * w;

    for (int i = t; i < 128 * 16; i += 256) {
        int n = i / 16, j = i % 16;
        *(uint4*)(sW0 + n * 68 + j * 4) = *(const uint4*)(g_nW0Tb + n * 64 + j * 4);
    }
    for (int i = t; i < 64 * 16; i += 256) {
        int n = i / 16, j = i % 16;
        *(uint4*)(sW1 + n * 68 + j * 4) = *(const uint4*)(g_nW1Tb + n * 64 + j * 4);
    }
    if (t < 128) sB0[t] = b0g[t];
    else if (t < 192) sB1[t - 128] = b1g[t - 128];
    __syncthreads();

    for (int tt = 0; tt < T_NODE; tt++) {
        int base = (blockIdx.x * T_NODE + tt) * 128;
        if (base >= N) break;
        if (tt) BAR128(1 + wm);
#pragma unroll
        for (int it = 0; it < 4; it++) {
            int row = GR + it * 4 + rsub;
            int n = min(base + row, N - 1);
            float inv = 1.0f / fmaxf(g_counts[n], 1.0f);
            const float* p0 = g_agg + (size_t)n * 64;
            const float* p1 = g_node + (size_t)n * 128 + 64;
            // agg chunk: read, scale, then zero in place (owner rows only)
            {
                float4 v0 = *(const float4*)(p0 + seg * 8);
                float4 v1 = *(const float4*)(p0 + seg * 8 + 4);
                if (base + row < N) {
                    *(float4*)(const_cast<float*>(p0) + seg * 8) = make_float4(0.f, 0.f, 0.f, 0.f);
                    *(float4*)(const_cast<float*>(p0) + seg * 8 + 4) = make_float4(0.f, 0.f, 0.f, 0.f);
                }
                v0.x *= inv; v0.y *= inv; v0.z *= inv; v0.w *= inv;
                v1.x *= inv; v1.y *= inv; v1.z *= inv; v1.w *= inv;
                uint4 u;
                u.x = pkbf(v0.x, v0.y); u.y = pkbf(v0.z, v0.w);
                u.z = pkbf(v1.x, v1.y); u.w = pkbf(v1.z, v1.w);
                *(uint4*)(sA + row * 68 + seg * 4) = u;
            }
            {
                float4 v0 = *(const float4*)(p1 + seg * 8);
                float4 v1 = *(const float4*)(p1 + seg * 8 + 4);
                uint4 u;
                u.x = pkbf(v0.x, v0.y); u.y = pkbf(v0.z, v0.w);
                u.z = pkbf(v1.x, v1.y); u.w = pkbf(v1.z, v1.w);
                *(uint4*)(sA + row * 68 + 32 + seg * 4) = u;
            }
        }
        BAR128(1 + wm);

        float d1[4][4][4];
#pragma unroll
        for (int m = 0; m < 4; m++)
#pragma unroll
            for (int n0 = 0; n0 < 4; n0++)
#pragma unroll
                for (int c = 0; c < 4; c++) d1[m][n0][c] = 0.f;

        for (int ks = 0; ks < 8; ks++) {
            uint32_t bf0[4], bf1[4];
#pragma unroll
            for (int n0 = 0; n0 < 4; n0++) {
                const uint32_t* bp = sW0 + (NB + n0 * 8 + lg) * 68 + ks * 8 + tg;
                bf0[n0] = bp[0]; bf1[n0] = bp[4];
            }
#pragma unroll
            for (int m = 0; m < 4; m++) {
                const uint32_t* ap = sA + (RB + m * 16 + lg) * 68 + ks * 8 + tg;
                uint32_t a0 = ap[0], a2 = ap[4], a1 = ap[544], a3 = ap[548];
#pragma unroll
                for (int n0 = 0; n0 < 4; n0++)
                    MMA16(d1[m][n0], a0, a1, a2, a3, bf0[n0], bf1[n0]);
            }
        }
        BAR128(1 + wm);

#pragma unroll
        for (int m = 0; m < 4; m++)
#pragma unroll
            for (int n0 = 0; n0 < 4; n0++) {
                int cb = NB + n0 * 8 + 2 * tg;
                float ba = sB0[cb], bb = sB0[cb + 1];
                float h0 = fmaxf(d1[m][n0][0] + ba, 0.f), h1 = fmaxf(d1[m][n0][1] + bb, 0.f);
                float h2 = fmaxf(d1[m][n0][2] + ba, 0.f), h3 = fmaxf(d1[m][n0][3] + bb, 0.f);
                int r = RB + m * 16 + lg;
                sA[r * 68 + (cb >> 1)] = pkbf(h0, h1);
                sA[(r + 8) * 68 + (cb >> 1)] = pkbf(h2, h3);
            }
        BAR128(1 + wm);

        float d2[4][2][4];
#pragma unroll
        for (int m = 0; m < 4; m++)
#pragma unroll
            for (int n0 = 0; n0 < 2; n0++)
#pragma unroll
                for (int c = 0; c < 4; c++) d2[m][n0][c] = 0.f;

        for (int ks = 0; ks < 8; ks++) {
            uint32_t bf0[2], bf1[2];
#pragma unroll
            for (int n0 = 0; n0 < 2; n0++) {
                const uint32_t* bp = sW1 + (NB2 + n0 * 8 + lg) * 68 + ks * 8 + tg;
                bf0[n0] = bp[0]; bf1[n0] = bp[4];
            }
#pragma unroll
            for (int m = 0; m < 4; m++) {
                const uint32_t* ap = sA + (RB + m * 16 + lg) * 68 + ks * 8 + tg;
                uint32_t a0 = ap[0], a2 = ap[4], a1 = ap[544], a3 = ap[548];
#pragma unroll
                for (int n0 = 0; n0 < 2; n0++)
                    MMA16(d2[m][n0], a0, a1, a2, a3, bf0[n0], bf1[n0]);
            }
        }

#pragma unroll
        for (int m = 0; m < 4; m++)
#pragma unroll
            for (int n0 = 0; n0 < 2; n0++) {
                int cb = NB2 + n0 * 8 + 2 * tg;
                float ba = sB1[cb], bb = sB1[cb + 1];
                int r0 = RB + m * 16 + lg;
                int nA = base + r0;
                if (nA < N) {
                    float* pn = g_node + (size_t)nA * 128 + 64 + cb;
                    float2 rv = *(const float2*)pn;
                    *(float2*)pn = make_float2(d2[m][n0][0] + ba + rv.x,
                                               d2[m][n0][1] + bb + rv.y);
                }
                int nB = base + r0 + 8;
                if (nB < N) {
                    float* pn = g_node + (size_t)nB * 128 + 64 + cb;
                    float2 rv = *(const float2*)pn;
                    *(float2*)pn = make_float2(d2[m][n0][2] + ba + rv.x,
                                               d2[m][n0][3] + bb + rv.y);
                }
            }
    }
}

// ---------------------------------------------------------------------------
// encode edge: layer1 tf32 (K=8, one step), layer2 bf16 m16n8k16
// smem u32: sW0f[128*12]=1536 | sW1b[64*68]=4352 | sA[128*68]=8704
// ---------------------------------------------------------------------------
#define T_ENC 8
#define EW1_OFF 1536
#define EA_OFF  5888
#define ESM_U32 (EA_OFF + 128 * 68)
__global__ void __launch_bounds__(256, 1)
k_encode_edge_mma(const float* __restrict__ ef, const float* __restrict__ b0g,
                  const float* __restrict__ b1g, int E) {
    extern __shared__ uint32_t smu[];
    float*    sW0 = (float*)smu;
    uint32_t* sW1 = smu + EW1_OFF;
    uint32_t* sAu = smu + EA_OFF;
    float*    sAf = (float*)sAu;
    int t = threadIdx.x, w = t >> 5, lane = t & 31;
    int tg = lane & 3, lg = lane >> 2, rb = 16 * w;

    for (int i = t; i < 128 * 2; i += 256) {
        int n = i / 2, j = i % 2;
        *(float4*)(sW0 + n * 12 + j * 4) = *(const float4*)(g_eW0T + n * 8 + j * 4);
    }
    for (int i = t; i < 64 * 16; i += 256) {
        int n = i / 16, j = i % 16;
        *(uint4*)(sW1 + n * 68 + j * 4) = *(const uint4*)(g_eW1Tb + n * 64 + j * 4);
    }
    __syncthreads();

    for (int tt = 0; tt < T_ENC; tt++) {
        int base = (blockIdx.x * T_ENC + tt) * 128;
        if (base >= E) break;
        int row = t >> 1, half = t & 1;
        int er = min(base + row, E - 1);
        {   // layer1 input (tf32 floats, k stride 1, row stride 68 floats)
            float* dst = sAf + row * 68 + half * 4;
            if (half == 0) {
                *(float4*)dst = make_float4(
                    __uint_as_float(f2tf(ef[er * 3 + 0])),
                    __uint_as_float(f2tf(ef[er * 3 + 1])),
                    __uint_as_float(f2tf(ef[er * 3 + 2])), 0.f);
            } else {
                *(float4*)dst = make_float4(0.f, 0.f, 0.f, 0.f);
            }
        }
        __syncwarp();

        float d1[16][4];
#pragma unroll
        for (int n0 = 0; n0 < 16; n0++)
#pragma unroll
            for (int c = 0; c < 4; c++) d1[n0][c] = 0.f;
        {
            uint32_t a0 = __float_as_uint(sAf[(rb + lg) * 68 + tg]);
            uint32_t a1 = __float_as_uint(sAf[(rb + lg + 8) * 68 + tg]);
            uint32_t a2 = __float_as_uint(sAf[(rb + lg) * 68 + tg + 4]);
            uint32_t a3 = __float_as_uint(sAf[(rb + lg + 8) * 68 + tg + 4]);
#pragma unroll
            for (int n0 = 0; n0 < 16; n0++) {
                uint32_t b0 = __float_as_uint(sW0[(n0 * 8 + lg) * 12 + tg]);
                uint32_t b1 = __float_as_uint(sW0[(n0 * 8 + lg) * 12 + tg + 4]);
                MMA8(d1[n0], a0, a1, a2, a3, b0, b1);
            }
        }
        __syncwarp();

        // h = relu(d1+b0) packed bf16 into sAu (row stride 68 u32, 64 kpairs)
#pragma unroll
        for (int n0 = 0; n0 < 16; n0++) {
            int c0 = n0 * 8 + 2 * tg;
            float ba = __ldg(b0g + c0), bb = __ldg(b0g + c0 + 1);
            float h0 = fmaxf(d1[n0][0] + ba, 0.f), h1 = fmaxf(d1[n0][1] + bb, 0.f);
            float h2 = fmaxf(d1[n0][2] + ba, 0.f), h3 = fmaxf(d1[n0][3] + bb, 0.f);
            sAu[(rb + lg) * 68 + (c0 >> 1)] = pkbf(h0, h1);
            sAu[(rb + lg + 8) * 68 + (c0 >> 1)] = pkbf(h2, h3);
        }
        __syncwarp();

        // layer2 bf16: h[16 rows x 128] @ W1 -> 16 rows x 64
        float d2[8][4];
#pragma unroll
        for (int n0 = 0; n0 < 8; n0++)
#pragma unroll
            for (int c = 0; c < 4; c++) d2[n0][c] = 0.f;
        for (int ks = 0; ks < 8; ks++) {
            const uint32_t* ap = sAu + (rb + lg) * 68 + ks * 8 + tg;
            uint32_t a0 = ap[0], a2 = ap[4], a1 = ap[544], a3 = ap[548];
#pragma unroll
            for (int n0 = 0; n0 < 8; n0++) {
                const uint32_t* bp = sW1 + (n0 * 8 + lg) * 68 + ks * 8 + tg;
                MMA16(d2[n0], a0, a1, a2, a3, bp[0], bp[4]);
            }
        }

        int r0 = rb + lg, r1 = r0 + 8;
#pragma unroll
        for (int n0 = 0; n0 < 8; n0++) {
            int c = n0 * 8 + 2 * tg;
            float ba = __ldg(b1g + c), bb = __ldg(b1g + c + 1);
            int e0 = base + r0;
            if (e0 < E)
                *(float2*)(g_edge_tail + (size_t)e0 * 64 + c) =
                    make_float2(d2[n0][0] + ba, d2[n0][1] + bb);
            int e1 = base + r1;
            if (e1 < E)
                *(float2*)(g_edge_tail + (size_t)e1 * 64 + c) =
                    make_float2(d2[n0][2] + ba, d2[n0][3] + bb);
        }
        __syncwarp();
    }
}

// ---------------- scalar fp32 encode_node / decode (unchanged) ----------------
__device__ __forceinline__ ull pk2(float a, float b) { ull r; asm("mov.b64 %0, {%1, %2};" : "=l"(r) : "f"(a), "f"(b)); return r; }
__device__ __forceinline__ void upk2(ull v, float &a, float &b) { asm("mov.b64 {%0, %1}, %2;" : "=f"(a), "=f"(b) : "l"(v)); }
__device__ __forceinline__ void fma2(ull &d, ull a, ull b) { asm("fma.rn.f32x2 %0, %1, %2, %3;" : "=l"(d) : "l"(a), "l"(b), "l"(d)); }
__device__ __forceinline__ void gemmA(ull (&acc)[4][4], const float* __restrict__ W, int ld, int K,
                                      const float* sInT, int c0, int r0) {
#pragma unroll 4
    for (int k = 0; k < K; k++) {
        float4 w = __ldg(reinterpret_cast<const float4*>(W + (size_t)k * ld + c0));
        ull w0 = pk2(w.x, w.x), w1 = pk2(w.y, w.y), w2 = pk2(w.z, w.z), w3 = pk2(w.w, w.w);
        const float* row = sInT + k * SROW + r0;
        ulonglong2 xa = *reinterpret_cast<const ulonglong2*>(row);
        ulonglong2 xb = *reinterpret_cast<const ulonglong2*>(row + 4);
        fma2(acc[0][0], xa.x, w0); fma2(acc[0][1], xa.x, w1); fma2(acc[0][2], xa.x, w2); fma2(acc[0][3], xa.x, w3);
        fma2(acc[1][0], xa.y, w0); fma2(acc[1][1], xa.y, w1); fma2(acc[1][2], xa.y, w2); fma2(acc[1][3], xa.y, w3);
        fma2(acc[2][0], xb.x, w0); fma2(acc[2][1], xb.x, w1); fma2(acc[2][2], xb.x, w2); fma2(acc[2][3], xb.x, w3);
        fma2(acc[3][0], xb.y, w0); fma2(acc[3][1], xb.y, w1); fma2(acc[3][2], xb.y, w2); fma2(acc[3][3], xb.y, w3);
    }
}
template <int NP>
__device__ __forceinline__ void init_bias(ull (&acc)[NP][4], const float* __restrict__ b, int c0) {
#pragma unroll
    for (int c = 0; c < 4; c++) {
        float bv = b[c0 + c]; ull bb = pk2(bv, bv);
#pragma unroll
        for (int p = 0; p < NP; p++) acc[p][c] = bb;
    }
}
__device__ __forceinline__ void relu_store_hT(ull (&acc)[4][4], float* sHT, int c0, int r0) {
#pragma unroll
    for (int p = 0; p < 4; p++)
#pragma unroll
        for (int c = 0; c < 4; c++) {
            float a, b; upk2(acc[p][c], a, b);
            *reinterpret_cast<float2*>(&sHT[(c0 + c) * SROW + r0 + 2 * p]) =
                make_float2(fmaxf(a, 0.f), fmaxf(b, 0.f));
        }
}

__global__ void __launch_bounds__(128)
k_encode_node(const float* __restrict__ nf, const float* __restrict__ emb,
              const float* __restrict__ W0, const float* __restrict__ b0,
              const float* __restrict__ W1, const float* __restrict__ b1, int N) {
    __shared__ float sInT[47 * SROW];
    __shared__ float sHT[128 * SROW];
    __shared__ int sPT[32];
    int t = threadIdx.x, base = blockIdx.x * 32;
    if (t < 32) { int n = min(base + t, N - 1); sPT[t] = (int)(nf[n * 32 + 31] + 0.5f); }
    __syncthreads();
    for (int i = t; i < 32 * 47; i += 128) {
        int r = i / 47, k = i - r * 47;
        int n = min(base + r, N - 1);
        sInT[k * SROW + r] = (k < 31) ? nf[n * 32 + k] : emb[sPT[r] * 16 + (k - 31)];
    }
    __syncthreads();
    int w = t >> 5, l = t & 31;
    int c0 = 32 * w + (l & 7) * 4, r0 = (l >> 3) * 8;
    ull acc[4][4];
    init_bias<4>(acc, b0, c0);
    gemmA(acc, W0, 128, 47, sInT, c0, r0);
    relu_store_hT(acc, sHT, c0, r0);
    __syncthreads();
    ull acc2[4][4];
    init_bias<4>(acc2, b1, c0);
    gemmA(acc2, W1, 128, 128, sHT, c0, r0);
#pragma unroll
    for (int p = 0; p < 4; p++)
#pragma unroll
        for (int c = 0; c < 4; c++) {
            float a, b; upk2(acc2[p][c], a, b);
            int rA = base + r0 + 2 * p;
            if (rA < N)     g_node[(size_t)rA * 128 + c0 + c] = a;
            if (rA + 1 < N) g_node[(size_t)(rA + 1) * 128 + c0 + c] = b;
        }
}

__global__ void __launch_bounds__(128)
k_decode(const float* __restrict__ W0, const float* __restrict__ b0,
         const float* __restrict__ W1, const float* __restrict__ b1,
         float* __restrict__ out, int N) {
    __shared__ float sInT[128 * SROW];
    __shared__ float sHT[128 * SROW];
    int t = threadIdx.x, base = blockIdx.x * 32;
    for (int i = t; i < 32 * 128; i += 128) {
        int r = i >> 7, k = i & 127;
        int n = min(base + r, N - 1);
        sInT[k * SROW + r] = g_node[(size_t)n * 128 + k];
    }
    __syncthreads();
    int w = t >> 5, l = t & 31;
    int c0 = 32 * w + (l & 7) * 4, r0 = (l >> 3) * 8;
    ull acc[4][4];
    init_bias<4>(acc, b0, c0);
    gemmA(acc, W0, 128, 128, sInT, c0, r0);
    relu_store_hT(acc, sHT, c0, r0);
    __syncthreads();
    if (t < 96) {
        int r = t / 3, c = t - 3 * (t / 3);
        float s = b1[c];
#pragma unroll 8
        for (int j = 0; j < 128; j++) s += sHT[j * SROW + r] * W1[j * 3 + c];
        int n = base + r;
        if (n < N) out[n * 3 + c] = s;
    }
}

// ---------------- launch ----------------
extern "C" void kernel_launch(void* const* d_in, const int* in_sizes, int n_in,
                              void* d_out, int out_size) {
    (void)n_in; (void)out_size;
    const int*   ei   = (const int*)d_in[0];
    const float* nf   = (const float*)d_in[1];
    const float* ef   = (const float*)d_in[2];
    const float* emb  = (const float*)d_in[3];
    const float* enW0 = (const float*)d_in[4],  *enb0 = (const float*)d_in[5];
    const float* enW1 = (const float*)d_in[6],  *enb1 = (const float*)d_in[7];
    const float* eeW0 = (const float*)d_in[8],  *eeb0 = (const float*)d_in[9];
    const float* eeW1 = (const float*)d_in[10], *eeb1 = (const float*)d_in[11];
    const float* ceW0 = (const float*)d_in[12], *ceb0 = (const float*)d_in[13];
    const float* ceW1 = (const float*)d_in[14], *ceb1 = (const float*)d_in[15];
    const float* cnW0 = (const float*)d_in[16], *cnb0 = (const float*)d_in[17];
    const float* cnW1 = (const float*)d_in[18], *cnb1 = (const float*)d_in[19];
    const float* dW0  = (const float*)d_in[20], *db0  = (const float*)d_in[21];
    const float* dW1  = (const float*)d_in[22], *db1  = (const float*)d_in[23];
    float* out = (float*)d_out;

    int N = in_sizes[1] / 32;
    int E = in_sizes[0] / 2;
    int nb = (N + 31) / 32;

    const int SM_CORE = CSM_U32 * 4;        // 121600
    const int SM_ENC  = ESM_U32 * 4;        // 58368
    const int SM_NODE = NSM_U32 * 4;        // 87808
    cudaFuncSetAttribute(k_edge_core_mma, cudaFuncAttributeMaxDynamicSharedMemorySize, SM_CORE);
    cudaFuncSetAttribute(k_encode_edge_mma, cudaFuncAttributeMaxDynamicSharedMemorySize, SM_ENC);
    cudaFuncSetAttribute(k_node_core_mma, cudaFuncAttributeMaxDynamicSharedMemorySize, SM_NODE);

    int prep_tot = 128 * 96 + 64 * 64 + 128 * 8 + 64 * 64 + 128 * 64 + 64 * 64;
    k_prep<<<(prep_tot + 255) / 256, 256>>>(ceW0, ceW1, eeW0, eeW1, cnW0, cnW1);
    k_zero_counts<<<(N + 255) / 256, 256>>>(N);
    k_counts<<<(E + 255) / 256, 256>>>(ei, E);
    k_zero_agg<<<(N * 64 + 255) / 256, 256>>>(N * 64);   // once; node_core re-zeroes
    k_encode_node<<<nb, 128>>>(nf, emb, enW0, enb0, enW1, enb1, N);

    int enc_b = (E + 128 * T_ENC - 1) / (128 * T_ENC);
    k_encode_edge_mma<<<enc_b, 256, SM_ENC>>>(ef, eeb0, eeb1 + 64, E);

    int core_b = (E + 128 * T_CORE - 1) / (128 * T_CORE);
    int node_b = (N + 128 * T_NODE - 1) / (128 * T_NODE);
    for (int s = 0; s < 3; s++) {
        k_edge_core_mma<<<core_b, 256, SM_CORE>>>(ei, ceb0, ceb1, E);
        k_node_core_mma<<<node_b, 256, SM_NODE>>>(cnb0, cnb1, N);
    }
    k_decode<<<nb, 128>>>(dW0, db0, dW1, db1, out, N);
}